// round 7
// baseline (speedup 1.0000x reference)
#include <cuda_runtime.h>
#include <cstdint>

// Problem constants
constexpr int Bn = 4;
constexpr int Sn = 2048;
constexpr int Dn = 1024;
constexpr int Hn = 16;
constexpr int HSn = 64;     // head size

constexpr int WSZ = Hn * Dn * HSn;         // one projection weight: 1M elems
constexpr int NX4 = Bn * Sn * Dn / 4;
constexpr int NW4 = WSZ / 4;

// Scratch. All hold tf32 BIT PATTERNS (as uint32).
__device__ uint32_t g_q[Bn * Hn * Sn * HSn];
__device__ uint32_t g_k[Bn * Hn * Sn * HSn];
__device__ uint32_t g_v[Bn * Hn * Sn * HSn];
__device__ uint32_t g_attn[Bn * Sn * Dn];
__device__ uint32_t g_xt[Bn * Sn * Dn];
__device__ uint32_t g_wt[3 * WSZ];
__device__ uint32_t g_wot[Dn * Dn];

// ---------------------------------------------------------------------------
// helpers
// ---------------------------------------------------------------------------
__device__ __forceinline__ uint32_t f2tf(float x) {
    uint32_t r;
    asm("cvt.rna.tf32.f32 %0, %1;" : "=r"(r) : "f"(x));
    return r;
}

__device__ __forceinline__ void mma_tf32(float c[4],
                                         uint32_t a0, uint32_t a1, uint32_t a2, uint32_t a3,
                                         uint32_t b0, uint32_t b1) {
    asm volatile(
        "mma.sync.aligned.m16n8k8.row.col.f32.tf32.tf32.f32 "
        "{%0,%1,%2,%3}, {%4,%5,%6,%7}, {%8,%9}, {%0,%1,%2,%3};\n"
        : "+f"(c[0]), "+f"(c[1]), "+f"(c[2]), "+f"(c[3])
        : "r"(a0), "r"(a1), "r"(a2), "r"(a3), "r"(b0), "r"(b1));
}

__device__ __forceinline__ void cp16(void* smem_dst, const void* gmem_src) {
    uint32_t d = (uint32_t)__cvta_generic_to_shared(smem_dst);
    asm volatile("cp.async.ca.shared.global [%0], [%1], 16;\n"
                 :: "r"(d), "l"(gmem_src));
}
#define CP_COMMIT() asm volatile("cp.async.commit_group;\n" ::: "memory")
#define CP_WAIT0()  asm volatile("cp.async.wait_group 0;\n" ::: "memory")
#define CP_WAIT1()  asm volatile("cp.async.wait_group 1;\n" ::: "memory")

// ---------------------------------------------------------------------------
// Kernel 0: fused fp32 -> tf32 conversion of X, Wq, Wk, Wv, Wo
// ---------------------------------------------------------------------------
__global__ __launch_bounds__(256) void cvt_all(
    const float4* __restrict__ X,  const float4* __restrict__ Wq,
    const float4* __restrict__ Wk, const float4* __restrict__ Wv,
    const float4* __restrict__ Wo)
{
    const int total = NX4 + 4 * NW4;
    int i = blockIdx.x * blockDim.x + threadIdx.x;
    const int stride = gridDim.x * blockDim.x;
    for (; i < total; i += stride) {
        const float4* s;
        uint4* d;
        int off;
        if (i < NX4)                { s = X;  d = (uint4*)g_xt;            off = i; }
        else if (i < NX4 + NW4)     { s = Wq; d = (uint4*)g_wt;            off = i - NX4; }
        else if (i < NX4 + 2 * NW4) { s = Wk; d = (uint4*)(g_wt + WSZ);    off = i - NX4 - NW4; }
        else if (i < NX4 + 3 * NW4) { s = Wv; d = (uint4*)(g_wt + 2*WSZ);  off = i - NX4 - 2*NW4; }
        else                        { s = Wo; d = (uint4*)g_wot;           off = i - NX4 - 3*NW4; }
        float4 v = s[off];
        d[off] = make_uint4(f2tf(v.x), f2tf(v.y), f2tf(v.z), f2tf(v.w));
    }
}

// ---------------------------------------------------------------------------
// GEMM template pieces: block tile 256(M) x 128(N), 8 warps (4 wm x 2 wn),
// warp tile 64x64 (4 mtiles x 8 ntiles). K chunk 16, double-buffered.
// Smem layouts (XOR-swizzled, no padding):
//   As[2][256][16], phys col = k ^ (((row>>1)&3)<<2)  -> conflict-free frags
//   Bs[2][16][128], phys col = n ^ ((krow&3)<<3)      -> conflict-free frags
// ---------------------------------------------------------------------------

// Kernel 1: merged QKV projection GEMM. grid = (24, B*S/256), block 256.
__global__ __launch_bounds__(256) void proj_tc()
{
    const int xx = blockIdx.x;
    const int which = xx >> 3;            // 0=q 1=k 2=v
    const int h0 = (xx & 7) * 2;
    const int m0 = blockIdx.y * 256;
    const int b = m0 >> 11;
    const int s0 = m0 & 2047;

    uint32_t* outb = (which == 0) ? g_q : (which == 1) ? g_k : g_v;
    const uint32_t* A = g_xt + (size_t)m0 * Dn;
    const uint32_t* B0 = g_wt + (size_t)which * WSZ + (size_t)h0 * Dn * HSn;

    __shared__ uint32_t As[2][256][16];
    __shared__ uint32_t Bs[2][16][128];

    const int tid = threadIdx.x;
    const int lane = tid & 31;
    const int w = tid >> 5;
    const int wm = w >> 1;     // 0..3
    const int wn = w & 1;      // 0..1
    const int g = lane >> 2;
    const int t4 = lane & 3;

    // fill mappings
    const int ar = tid;                  // 0..255, one row per thread
    const int awz = ((ar >> 1) & 3) << 2;
    const int bk = tid >> 4;             // 0..15
    const int bn = (tid & 15) * 8;
    const int bwz = (bk & 3) << 3;
    const uint32_t* Bsrc = B0 + (bn < 64 ? bn : (size_t)Dn * HSn + (bn - 64));
    const uint32_t* Arow = A + (size_t)ar * Dn;

    // fragment-read swizzle (constant per lane)
    const int rwz = (g >> 1) << 2;

    float c[4][8][4] = {};

    // prime stage 0 with chunk 0
    #pragma unroll
    for (int cc = 0; cc < 16; cc += 4)
        cp16(&As[0][ar][cc ^ awz], Arow + cc);
    cp16(&Bs[0][bk][bn ^ bwz],       Bsrc + bk * HSn);
    cp16(&Bs[0][bk][(bn ^ bwz) + 4], Bsrc + bk * HSn + 4);
    CP_COMMIT();
    CP_WAIT0();
    __syncthreads();

    int buf = 0;
    for (int ch = 0; ch < 64; ch++) {
        const bool more = (ch + 1 < 64);
        if (more) {
            const int kc = (ch + 1) * 16;
            const int nb = buf ^ 1;
            #pragma unroll
            for (int cc = 0; cc < 16; cc += 4)
                cp16(&As[nb][ar][cc ^ awz], Arow + kc + cc);
            cp16(&Bs[nb][bk][bn ^ bwz],       Bsrc + (kc + bk) * HSn);
            cp16(&Bs[nb][bk][(bn ^ bwz) + 4], Bsrc + (kc + bk) * HSn + 4);
            CP_COMMIT();
        }

        #pragma unroll
        for (int ks = 0; ks < 2; ks++) {
            const int k = ks * 8 + t4;
            const int pk = k ^ rwz;
            const int pk4 = pk ^ 4;
            uint32_t a[4][4];
            #pragma unroll
            for (int mt = 0; mt < 4; mt++) {
                const int r = wm * 64 + mt * 16 + g;
                a[mt][0] = As[buf][r][pk];
                a[mt][1] = As[buf][r + 8][pk];
                a[mt][2] = As[buf][r][pk4];
                a[mt][3] = As[buf][r + 8][pk4];
            }
            #pragma unroll
            for (int nt = 0; nt < 8; nt++) {
                const int pn = wn * 64 + ((nt ^ t4) << 3) + g;
                uint32_t b0 = Bs[buf][k][pn];
                uint32_t b1 = Bs[buf][k + 4][pn];
                #pragma unroll
                for (int mt = 0; mt < 4; mt++)
                    mma_tf32(c[mt][nt], a[mt][0], a[mt][1], a[mt][2], a[mt][3], b0, b1);
            }
        }

        if (more) CP_WAIT0();
        __syncthreads();
        buf ^= 1;
    }

    // epilogue: head = h0 + wn; Q pre-scaled by 0.125; all tf32-rounded bits
    const float sc = (which == 0) ? 0.125f : 1.0f;
    uint32_t* O = outb + ((size_t)(b * Hn + h0 + wn) * Sn + s0) * HSn;
    #pragma unroll
    for (int mt = 0; mt < 4; mt++) {
        const int r = wm * 64 + mt * 16 + g;
        #pragma unroll
        for (int nt = 0; nt < 8; nt++) {
            const int hs = nt * 8 + 2 * t4;
            *(uint2*)&O[(size_t)r * HSn + hs] =
                make_uint2(f2tf(c[mt][nt][0] * sc), f2tf(c[mt][nt][1] * sc));
            *(uint2*)&O[(size_t)(r + 8) * HSn + hs] =
                make_uint2(f2tf(c[mt][nt][2] * sc), f2tf(c[mt][nt][3] * sc));
        }
    }
}

// ---------------------------------------------------------------------------
// Kernel 2: causal flash attention. BM=256, BN=32, 8 warps x 32 rows.
// K/V fragments reused across 2 mtiles -> half the smem traffic per MAC.
// grid = (S/256, B*H), block = 256
// ---------------------------------------------------------------------------
__global__ __launch_bounds__(256) void attn_tc()
{
    const int qt = blockIdx.x;    // 0..7
    const int bh = blockIdx.y;
    const int b = bh >> 4;
    const int h = bh & 15;
    const int q0 = qt * 256;

    const uint32_t* Q = g_q + (size_t)(bh * Sn + q0) * HSn;
    const uint32_t* K = g_k + (size_t)bh * Sn * HSn;
    const uint32_t* V = g_v + (size_t)bh * Sn * HSn;

    __shared__ uint32_t Ks[2][32][68];
    __shared__ uint32_t Vs[2][32][72];

    const int tid = threadIdx.x;
    const int lane = tid & 31;
    const int w = tid >> 5;
    const int g = lane >> 2;
    const int t4 = lane & 3;
    const int wrow = w * 32;          // warp's first of 32 rows

    // Q fragments for 2 mtiles (pre-scaled tf32 bits from proj)
    uint32_t qf[2][8][4];
    #pragma unroll
    for (int mt = 0; mt < 2; mt++) {
        const uint32_t* Qw = Q + (size_t)(wrow + mt * 16 + g) * HSn;
        #pragma unroll
        for (int ks = 0; ks < 8; ks++) {
            const int e = ks * 8 + t4;
            qf[mt][ks][0] = Qw[e];
            qf[mt][ks][1] = Qw[8 * HSn + e];
            qf[mt][ks][2] = Qw[e + 4];
            qf[mt][ks][3] = Qw[8 * HSn + e + 4];
        }
    }

    float o[2][8][4] = {};
    float mm[2][2] = {{-1e30f, -1e30f}, {-1e30f, -1e30f}};
    float ll[2][2] = {{0.0f, 0.0f}, {0.0f, 0.0f}};

    const int kn = tid >> 3;            // 0..31
    const int ke = (tid & 7) * 8;
    const int rmax = q0 + wrow + 31;
    const int jmax = 8 * qt + 7;

    // shuffle relayout lanes (C-frag -> A-frag, intra-quad)
    const int srcA = (lane & ~3) | (t4 >> 1);
    const int srcB = srcA + 2;
    const bool hi = (t4 & 1) != 0;

    // prime stage 0 with tile 0
    {
        const uint32_t* kp = K + (size_t)kn * HSn + ke;
        const uint32_t* vp = V + (size_t)kn * HSn + ke;
        cp16(&Ks[0][kn][ke], kp);     cp16(&Ks[0][kn][ke + 4], kp + 4);
        cp16(&Vs[0][kn][ke], vp);     cp16(&Vs[0][kn][ke + 4], vp + 4);
        CP_COMMIT();
    }

    for (int j = 0; j <= jmax; j++) {
        const int st = j & 1;
        const int k0 = j * 32;

        if (j < jmax) {
            const int kc = (j + 1) * 32;
            const uint32_t* kp = K + (size_t)(kc + kn) * HSn + ke;
            const uint32_t* vp = V + (size_t)(kc + kn) * HSn + ke;
            cp16(&Ks[st ^ 1][kn][ke], kp);  cp16(&Ks[st ^ 1][kn][ke + 4], kp + 4);
            cp16(&Vs[st ^ 1][kn][ke], vp);  cp16(&Vs[st ^ 1][kn][ke + 4], vp + 4);
            CP_COMMIT();
            CP_WAIT1();
        } else {
            CP_WAIT0();
        }
        __syncthreads();

        if (k0 <= rmax) {
            // S = Q @ K^T  (both mtiles share each K fragment)
            float s[2][4][4] = {};
            #pragma unroll
            for (int ks = 0; ks < 8; ks++) {
                const int e = ks * 8 + t4;
                #pragma unroll
                for (int nt = 0; nt < 4; nt++) {
                    const int n = nt * 8 + g;
                    uint32_t b0 = Ks[st][n][e];
                    uint32_t b1 = Ks[st][n][e + 4];
                    mma_tf32(s[0][nt], qf[0][ks][0], qf[0][ks][1], qf[0][ks][2], qf[0][ks][3], b0, b1);
                    mma_tf32(s[1][nt], qf[1][ks][0], qf[1][ks][1], qf[1][ks][2], qf[1][ks][3], b0, b1);
                }
            }

            uint32_t pt[2][4][4];
            #pragma unroll
            for (int mt = 0; mt < 2; mt++) {
                // causal mask
                const int r0g = q0 + wrow + mt * 16 + g;
                const int r1g = r0g + 8;
                #pragma unroll
                for (int nt = 0; nt < 4; nt++) {
                    const int kc0 = k0 + nt * 8 + 2 * t4;
                    if (kc0 > r0g)     s[mt][nt][0] = -1e30f;
                    if (kc0 + 1 > r0g) s[mt][nt][1] = -1e30f;
                    if (kc0 > r1g)     s[mt][nt][2] = -1e30f;
                    if (kc0 + 1 > r1g) s[mt][nt][3] = -1e30f;
                }

                // online softmax (warp-local rows)
                float mx0 = -1e30f, mx1 = -1e30f;
                #pragma unroll
                for (int nt = 0; nt < 4; nt++) {
                    mx0 = fmaxf(mx0, fmaxf(s[mt][nt][0], s[mt][nt][1]));
                    mx1 = fmaxf(mx1, fmaxf(s[mt][nt][2], s[mt][nt][3]));
                }
                mx0 = fmaxf(mx0, __shfl_xor_sync(0xffffffffu, mx0, 1));
                mx0 = fmaxf(mx0, __shfl_xor_sync(0xffffffffu, mx0, 2));
                mx1 = fmaxf(mx1, __shfl_xor_sync(0xffffffffu, mx1, 1));
                mx1 = fmaxf(mx1, __shfl_xor_sync(0xffffffffu, mx1, 2));

                const float mn0 = fmaxf(mm[mt][0], mx0);
                const float mn1 = fmaxf(mm[mt][1], mx1);
                const float al0 = __expf(mm[mt][0] - mn0);
                const float al1 = __expf(mm[mt][1] - mn1);
                mm[mt][0] = mn0; mm[mt][1] = mn1;

                float sum0 = 0.0f, sum1 = 0.0f;
                #pragma unroll
                for (int nt = 0; nt < 4; nt++) {
                    float p0 = __expf(s[mt][nt][0] - mn0);
                    float p1 = __expf(s[mt][nt][1] - mn0);
                    float p2 = __expf(s[mt][nt][2] - mn1);
                    float p3 = __expf(s[mt][nt][3] - mn1);
                    pt[mt][nt][0] = f2tf(p0); pt[mt][nt][1] = f2tf(p1);
                    pt[mt][nt][2] = f2tf(p2); pt[mt][nt][3] = f2tf(p3);
                    sum0 += __uint_as_float(pt[mt][nt][0]) + __uint_as_float(pt[mt][nt][1]);
                    sum1 += __uint_as_float(pt[mt][nt][2]) + __uint_as_float(pt[mt][nt][3]);
                }
                sum0 += __shfl_xor_sync(0xffffffffu, sum0, 1);
                sum0 += __shfl_xor_sync(0xffffffffu, sum0, 2);
                sum1 += __shfl_xor_sync(0xffffffffu, sum1, 1);
                sum1 += __shfl_xor_sync(0xffffffffu, sum1, 2);
                ll[mt][0] = ll[mt][0] * al0 + sum0;
                ll[mt][1] = ll[mt][1] * al1 + sum1;

                #pragma unroll
                for (int nt = 0; nt < 8; nt++) {
                    o[mt][nt][0] *= al0; o[mt][nt][1] *= al0;
                    o[mt][nt][2] *= al1; o[mt][nt][3] *= al1;
                }
            }

            // O += P @ V  (both mtiles share each V fragment)
            #pragma unroll
            for (int ks = 0; ks < 4; ks++) {
                uint32_t aa[2][4];
                #pragma unroll
                for (int mt = 0; mt < 2; mt++) {
                    uint32_t p0a = __shfl_sync(0xffffffffu, pt[mt][ks][0], srcA);
                    uint32_t p1a = __shfl_sync(0xffffffffu, pt[mt][ks][1], srcA);
                    uint32_t p2a = __shfl_sync(0xffffffffu, pt[mt][ks][2], srcA);
                    uint32_t p3a = __shfl_sync(0xffffffffu, pt[mt][ks][3], srcA);
                    uint32_t p0b = __shfl_sync(0xffffffffu, pt[mt][ks][0], srcB);
                    uint32_t p1b = __shfl_sync(0xffffffffu, pt[mt][ks][1], srcB);
                    uint32_t p2b = __shfl_sync(0xffffffffu, pt[mt][ks][2], srcB);
                    uint32_t p3b = __shfl_sync(0xffffffffu, pt[mt][ks][3], srcB);
                    aa[mt][0] = hi ? p1a : p0a;
                    aa[mt][1] = hi ? p3a : p2a;
                    aa[mt][2] = hi ? p1b : p0b;
                    aa[mt][3] = hi ? p3b : p2b;
                }
                const int k = ks * 8 + t4;
                #pragma unroll
                for (int nt = 0; nt < 8; nt++) {
                    const int hs = nt * 8 + g;
                    uint32_t b0 = Vs[st][k][hs];
                    uint32_t b1 = Vs[st][k + 4][hs];
                    mma_tf32(o[0][nt], aa[0][0], aa[0][1], aa[0][2], aa[0][3], b0, b1);
                    mma_tf32(o[1][nt], aa[1][0], aa[1][1], aa[1][2], aa[1][3], b0, b1);
                }
            }
        }
        __syncthreads();
    }

    // normalize + write (tf32-rounded bits) to concat-head layout [B,S,D]
    uint32_t* Ob = g_attn + (size_t)(b * Sn) * Dn + h * HSn;
    #pragma unroll
    for (int mt = 0; mt < 2; mt++) {
        const float inv0 = 1.0f / ll[mt][0];
        const float inv1 = 1.0f / ll[mt][1];
        const int row = q0 + wrow + mt * 16 + g;
        #pragma unroll
        for (int nt = 0; nt < 8; nt++) {
            const int hs = nt * 8 + 2 * t4;
            *(uint2*)&Ob[(size_t)row * Dn + hs] =
                make_uint2(f2tf(o[mt][nt][0] * inv0), f2tf(o[mt][nt][1] * inv0));
            *(uint2*)&Ob[(size_t)(row + 8) * Dn + hs] =
                make_uint2(f2tf(o[mt][nt][2] * inv1), f2tf(o[mt][nt][3] * inv1));
        }
    }
}

// ---------------------------------------------------------------------------
// Kernel 3: output projection. Same 256x128 swizzled template.
// grid = (D/128, B*S/256), block = 256
// ---------------------------------------------------------------------------
__global__ __launch_bounds__(256) void outproj_tc(
    const float* __restrict__ bo,
    float* __restrict__ out)
{
    const int nt0 = blockIdx.x * 128;
    const int m0 = blockIdx.y * 256;
    const uint32_t* A = g_attn + (size_t)m0 * Dn;

    __shared__ uint32_t As[2][256][16];
    __shared__ uint32_t Bs[2][16][128];

    const int tid = threadIdx.x;
    const int lane = tid & 31;
    const int w = tid >> 5;
    const int wm = w >> 1;
    const int wn = w & 1;
    const int g = lane >> 2;
    const int t4 = lane & 3;

    const int ar = tid;
    const int awz = ((ar >> 1) & 3) << 2;
    const int bk = tid >> 4;
    const int bn = (tid & 15) * 8;
    const int bwz = (bk & 3) << 3;
    const uint32_t* Arow = A + (size_t)ar * Dn;
    const uint32_t* Bsrc = g_wot + nt0 + bn;

    const int rwz = (g >> 1) << 2;

    float c[4][8][4] = {};

    #pragma unroll
    for (int cc = 0; cc < 16; cc += 4)
        cp16(&As[0][ar][cc ^ awz], Arow + cc);
    cp16(&Bs[0][bk][bn ^ bwz],       Bsrc + (size_t)bk * Dn);
    cp16(&Bs[0][bk][(bn ^ bwz) + 4], Bsrc + (size_t)bk * Dn + 4);
    CP_COMMIT();
    CP_WAIT0();
    __syncthreads();

    int buf = 0;
    for (int ch = 0; ch < 64; ch++) {
        const bool more = (ch + 1 < 64);
        if (more) {
            const int kc = (ch + 1) * 16;
            const int nb = buf ^ 1;
            #pragma unroll
            for (int cc = 0; cc < 16; cc += 4)
                cp16(&As[nb][ar][cc ^ awz], Arow + kc + cc);
            cp16(&Bs[nb][bk][bn ^ bwz],       Bsrc + (size_t)(kc + bk) * Dn);
            cp16(&Bs[nb][bk][(bn ^ bwz) + 4], Bsrc + (size_t)(kc + bk) * Dn + 4);
            CP_COMMIT();
        }

        #pragma unroll
        for (int ks = 0; ks < 2; ks++) {
            const int k = ks * 8 + t4;
            const int pk = k ^ rwz;
            const int pk4 = pk ^ 4;
            uint32_t a[4][4];
            #pragma unroll
            for (int mt = 0; mt < 4; mt++) {
                const int r = wm * 64 + mt * 16 + g;
                a[mt][0] = As[buf][r][pk];
                a[mt][1] = As[buf][r + 8][pk];
                a[mt][2] = As[buf][r][pk4];
                a[mt][3] = As[buf][r + 8][pk4];
            }
            #pragma unroll
            for (int nt = 0; nt < 8; nt++) {
                const int pn = wn * 64 + ((nt ^ t4) << 3) + g;
                uint32_t b0 = Bs[buf][k][pn];
                uint32_t b1 = Bs[buf][k + 4][pn];
                #pragma unroll
                for (int mt = 0; mt < 4; mt++)
                    mma_tf32(c[mt][nt], a[mt][0], a[mt][1], a[mt][2], a[mt][3], b0, b1);
            }
        }

        if (more) CP_WAIT0();
        __syncthreads();
        buf ^= 1;
    }

    float* C = out + (size_t)m0 * Dn + nt0;
    #pragma unroll
    for (int mt = 0; mt < 4; mt++) {
        const int r = wm * 64 + mt * 16 + g;
        #pragma unroll
        for (int nt = 0; nt < 8; nt++) {
            const int n = wn * 64 + nt * 8 + 2 * t4;
            const float2 bias = *(const float2*)&bo[nt0 + n];
            *(float2*)&C[(size_t)r * Dn + n] =
                make_float2(c[mt][nt][0] + bias.x, c[mt][nt][1] + bias.y);
            *(float2*)&C[(size_t)(r + 8) * Dn + n] =
                make_float2(c[mt][nt][2] + bias.x, c[mt][nt][3] + bias.y);
        }
    }
}

// ---------------------------------------------------------------------------
extern "C" void kernel_launch(void* const* d_in, const int* in_sizes, int n_in,
                              void* d_out, int out_size)
{
    const float* X  = (const float*)d_in[0];
    const float* Wq = (const float*)d_in[1];
    const float* Wk = (const float*)d_in[2];
    const float* Wv = (const float*)d_in[3];
    const float* Wo = (const float*)d_in[4];
    const float* bo = (const float*)d_in[5];
    float* out = (float*)d_out;

    cvt_all<<<2048, 256>>>((const float4*)X, (const float4*)Wq,
                           (const float4*)Wk, (const float4*)Wv,
                           (const float4*)Wo);
    proj_tc<<<dim3(24, (Bn * Sn) / 256), 256>>>();
    attn_tc<<<dim3(Sn / 256, Bn * Hn), 256>>>();
    outproj_tc<<<dim3(Dn / 128, (Bn * Sn) / 256), 256>>>(bo, out);
}

// round 8
// speedup vs baseline: 1.1021x; 1.1021x over previous
#include <cuda_runtime.h>
#include <cstdint>

// Problem constants
constexpr int Bn = 4;
constexpr int Sn = 2048;
constexpr int Dn = 1024;
constexpr int Hn = 16;
constexpr int HSn = 64;     // head size

constexpr int WSZ = Hn * Dn * HSn;         // one projection weight: 1M elems
constexpr int NX4 = Bn * Sn * Dn / 4;
constexpr int NW4 = WSZ / 4;

// Scratch. All hold tf32 BIT PATTERNS (as uint32).
__device__ uint32_t g_q[Bn * Hn * Sn * HSn];
__device__ uint32_t g_k[Bn * Hn * Sn * HSn];
__device__ uint32_t g_v[Bn * Hn * Sn * HSn];
__device__ uint32_t g_attn[Bn * Sn * Dn];
__device__ uint32_t g_xt[Bn * Sn * Dn];
__device__ uint32_t g_wt[3 * WSZ];
__device__ uint32_t g_wot[Dn * Dn];

// ---------------------------------------------------------------------------
// helpers
// ---------------------------------------------------------------------------
__device__ __forceinline__ uint32_t f2tf(float x) {
    uint32_t r;
    asm("cvt.rna.tf32.f32 %0, %1;" : "=r"(r) : "f"(x));
    return r;
}

__device__ __forceinline__ void mma_tf32(float c[4],
                                         uint32_t a0, uint32_t a1, uint32_t a2, uint32_t a3,
                                         uint32_t b0, uint32_t b1) {
    asm volatile(
        "mma.sync.aligned.m16n8k8.row.col.f32.tf32.tf32.f32 "
        "{%0,%1,%2,%3}, {%4,%5,%6,%7}, {%8,%9}, {%0,%1,%2,%3};\n"
        : "+f"(c[0]), "+f"(c[1]), "+f"(c[2]), "+f"(c[3])
        : "r"(a0), "r"(a1), "r"(a2), "r"(a3), "r"(b0), "r"(b1));
}

__device__ __forceinline__ void cp16(void* smem_dst, const void* gmem_src) {
    uint32_t d = (uint32_t)__cvta_generic_to_shared(smem_dst);
    asm volatile("cp.async.ca.shared.global [%0], [%1], 16;\n"
                 :: "r"(d), "l"(gmem_src));
}
#define CP_COMMIT() asm volatile("cp.async.commit_group;\n" ::: "memory")
#define CP_WAIT0()  asm volatile("cp.async.wait_group 0;\n" ::: "memory")
#define CP_WAIT1()  asm volatile("cp.async.wait_group 1;\n" ::: "memory")

// ---------------------------------------------------------------------------
// Kernel 0: fused fp32 -> tf32 conversion of X, Wq, Wk, Wv, Wo
// ---------------------------------------------------------------------------
__global__ __launch_bounds__(256) void cvt_all(
    const float4* __restrict__ X,  const float4* __restrict__ Wq,
    const float4* __restrict__ Wk, const float4* __restrict__ Wv,
    const float4* __restrict__ Wo)
{
    const int total = NX4 + 4 * NW4;
    int i = blockIdx.x * blockDim.x + threadIdx.x;
    const int stride = gridDim.x * blockDim.x;
    for (; i < total; i += stride) {
        const float4* s;
        uint4* d;
        int off;
        if (i < NX4)                { s = X;  d = (uint4*)g_xt;            off = i; }
        else if (i < NX4 + NW4)     { s = Wq; d = (uint4*)g_wt;            off = i - NX4; }
        else if (i < NX4 + 2 * NW4) { s = Wk; d = (uint4*)(g_wt + WSZ);    off = i - NX4 - NW4; }
        else if (i < NX4 + 3 * NW4) { s = Wv; d = (uint4*)(g_wt + 2*WSZ);  off = i - NX4 - 2*NW4; }
        else                        { s = Wo; d = (uint4*)g_wot;           off = i - NX4 - 3*NW4; }
        float4 v = s[off];
        d[off] = make_uint4(f2tf(v.x), f2tf(v.y), f2tf(v.z), f2tf(v.w));
    }
}

// ---------------------------------------------------------------------------
// Kernel 1: merged QKV projection GEMM (R6 structure, 3 blocks/SM target).
// Block tile 128x128 (2 heads). 8 warps (4x2), warp tile 32x64. K chunk 16.
// grid = (24, B*S/128), block = 256
// ---------------------------------------------------------------------------
__global__ __launch_bounds__(256, 3) void proj_tc()
{
    const int xx = blockIdx.x;
    const int which = xx >> 3;
    const int h0 = (xx & 7) * 2;
    const int m0 = blockIdx.y * 128;
    const int b = m0 >> 11;
    const int s0 = m0 & 2047;

    uint32_t* outb = (which == 0) ? g_q : (which == 1) ? g_k : g_v;
    const uint32_t* A = g_xt + (size_t)m0 * Dn;
    const uint32_t* B0 = g_wt + (size_t)which * WSZ + (size_t)h0 * Dn * HSn;

    __shared__ uint32_t As[2][128][20];
    __shared__ uint32_t Bs[2][16][136];

    const int tid = threadIdx.x;
    const int lane = tid & 31;
    const int w = tid >> 5;
    const int wm = w >> 1;
    const int wn = w & 1;
    const int g = lane >> 2;
    const int t4 = lane & 3;

    const int ar = tid >> 1;
    const int ac = (tid & 1) * 8;
    const int bk = tid >> 4;
    const int bn = (tid & 15) * 8;
    const uint32_t* Bsrc = B0 + (bn < 64 ? bn : (size_t)Dn * HSn + (bn - 64));
    const uint32_t* Arow = A + (size_t)ar * Dn + ac;

    float c[2][8][4] = {};

    cp16(&As[0][ar][ac],     Arow);
    cp16(&As[0][ar][ac + 4], Arow + 4);
    cp16(&Bs[0][bk][bn],     Bsrc + bk * HSn);
    cp16(&Bs[0][bk][bn + 4], Bsrc + bk * HSn + 4);
    CP_COMMIT();
    CP_WAIT0();
    __syncthreads();

    int buf = 0;
    for (int ch = 0; ch < 64; ch++) {
        const bool more = (ch + 1 < 64);
        if (more) {
            const int kc = (ch + 1) * 16;
            const int nb = buf ^ 1;
            cp16(&As[nb][ar][ac],     Arow + kc);
            cp16(&As[nb][ar][ac + 4], Arow + kc + 4);
            cp16(&Bs[nb][bk][bn],     Bsrc + (kc + bk) * HSn);
            cp16(&Bs[nb][bk][bn + 4], Bsrc + (kc + bk) * HSn + 4);
            CP_COMMIT();
        }

        #pragma unroll
        for (int ks = 0; ks < 2; ks++) {
            const int k = ks * 8 + t4;
            uint32_t a[2][4];
            #pragma unroll
            for (int mt = 0; mt < 2; mt++) {
                const int r = wm * 32 + mt * 16 + g;
                a[mt][0] = As[buf][r][k];
                a[mt][1] = As[buf][r + 8][k];
                a[mt][2] = As[buf][r][k + 4];
                a[mt][3] = As[buf][r + 8][k + 4];
            }
            #pragma unroll
            for (int nt = 0; nt < 8; nt++) {
                const int n = wn * 64 + nt * 8 + g;
                uint32_t b0 = Bs[buf][k][n];
                uint32_t b1 = Bs[buf][k + 4][n];
                mma_tf32(c[0][nt], a[0][0], a[0][1], a[0][2], a[0][3], b0, b1);
                mma_tf32(c[1][nt], a[1][0], a[1][1], a[1][2], a[1][3], b0, b1);
            }
        }

        if (more) CP_WAIT0();
        __syncthreads();
        buf ^= 1;
    }

    const float sc = (which == 0) ? 0.125f : 1.0f;
    uint32_t* O = outb + ((size_t)(b * Hn + h0 + wn) * Sn + s0) * HSn;
    #pragma unroll
    for (int mt = 0; mt < 2; mt++) {
        const int r = wm * 32 + mt * 16 + g;
        #pragma unroll
        for (int nt = 0; nt < 8; nt++) {
            const int hs = nt * 8 + 2 * t4;
            *(uint2*)&O[(size_t)r * HSn + hs] =
                make_uint2(f2tf(c[mt][nt][0] * sc), f2tf(c[mt][nt][1] * sc));
            *(uint2*)&O[(size_t)(r + 8) * HSn + hs] =
                make_uint2(f2tf(c[mt][nt][2] * sc), f2tf(c[mt][nt][3] * sc));
        }
    }
}

// ---------------------------------------------------------------------------
// Kernel 2: causal flash attention (R6 structure, 2 blocks/SM guaranteed,
// reversed qt order for LPT scheduling). BM=128, BN=32, 8 warps along M.
// grid = (S/128, B*H), block = 256
// ---------------------------------------------------------------------------
__global__ __launch_bounds__(256, 2) void attn_tc()
{
    const int qt = (int)gridDim.x - 1 - (int)blockIdx.x;   // heavy blocks first
    const int bh = blockIdx.y;
    const int b = bh >> 4;
    const int h = bh & 15;
    const int q0 = qt * 128;

    const uint32_t* Q = g_q + (size_t)(bh * Sn + q0) * HSn;
    const uint32_t* K = g_k + (size_t)bh * Sn * HSn;
    const uint32_t* V = g_v + (size_t)bh * Sn * HSn;

    __shared__ uint32_t Ks[2][32][68];
    __shared__ uint32_t Vs[2][32][72];

    const int tid = threadIdx.x;
    const int lane = tid & 31;
    const int w = tid >> 5;
    const int g = lane >> 2;
    const int t4 = lane & 3;
    const int wrow = w * 16;

    uint32_t qf[8][4];
    {
        const uint32_t* Qw = Q + (size_t)(wrow + g) * HSn;
        #pragma unroll
        for (int ks = 0; ks < 8; ks++) {
            const int e = ks * 8 + t4;
            qf[ks][0] = Qw[e];
            qf[ks][1] = Qw[8 * HSn + e];
            qf[ks][2] = Qw[e + 4];
            qf[ks][3] = Qw[8 * HSn + e + 4];
        }
    }

    float o[8][4] = {};
    float m0 = -1e30f, m1 = -1e30f, l0 = 0.0f, l1 = 0.0f;

    const int kn = tid >> 3;
    const int ke = (tid & 7) * 8;
    const int rmax = q0 + wrow + 15;
    const int jmax = 4 * qt + 3;

    const int srcA = (lane & ~3) | (t4 >> 1);
    const int srcB = srcA + 2;
    const bool hi = (t4 & 1) != 0;

    {
        const uint32_t* kp = K + (size_t)kn * HSn + ke;
        const uint32_t* vp = V + (size_t)kn * HSn + ke;
        cp16(&Ks[0][kn][ke], kp);     cp16(&Ks[0][kn][ke + 4], kp + 4);
        cp16(&Vs[0][kn][ke], vp);     cp16(&Vs[0][kn][ke + 4], vp + 4);
        CP_COMMIT();
    }

    for (int j = 0; j <= jmax; j++) {
        const int st = j & 1;
        const int k0 = j * 32;

        if (j < jmax) {
            const int kc = (j + 1) * 32;
            const uint32_t* kp = K + (size_t)(kc + kn) * HSn + ke;
            const uint32_t* vp = V + (size_t)(kc + kn) * HSn + ke;
            cp16(&Ks[st ^ 1][kn][ke], kp);  cp16(&Ks[st ^ 1][kn][ke + 4], kp + 4);
            cp16(&Vs[st ^ 1][kn][ke], vp);  cp16(&Vs[st ^ 1][kn][ke + 4], vp + 4);
            CP_COMMIT();
            CP_WAIT1();
        } else {
            CP_WAIT0();
        }
        __syncthreads();

        if (k0 <= rmax) {
            float s[4][4] = {};
            #pragma unroll
            for (int ks = 0; ks < 8; ks++) {
                const int e = ks * 8 + t4;
                #pragma unroll
                for (int nt = 0; nt < 4; nt++) {
                    const int n = nt * 8 + g;
                    uint32_t b0 = Ks[st][n][e];
                    uint32_t b1 = Ks[st][n][e + 4];
                    mma_tf32(s[nt], qf[ks][0], qf[ks][1], qf[ks][2], qf[ks][3], b0, b1);
                }
            }

            const int r0g = q0 + wrow + g;
            const int r1g = r0g + 8;
            #pragma unroll
            for (int nt = 0; nt < 4; nt++) {
                const int kc0 = k0 + nt * 8 + 2 * t4;
                if (kc0 > r0g)     s[nt][0] = -1e30f;
                if (kc0 + 1 > r0g) s[nt][1] = -1e30f;
                if (kc0 > r1g)     s[nt][2] = -1e30f;
                if (kc0 + 1 > r1g) s[nt][3] = -1e30f;
            }

            float mx0 = -1e30f, mx1 = -1e30f;
            #pragma unroll
            for (int nt = 0; nt < 4; nt++) {
                mx0 = fmaxf(mx0, fmaxf(s[nt][0], s[nt][1]));
                mx1 = fmaxf(mx1, fmaxf(s[nt][2], s[nt][3]));
            }
            mx0 = fmaxf(mx0, __shfl_xor_sync(0xffffffffu, mx0, 1));
            mx0 = fmaxf(mx0, __shfl_xor_sync(0xffffffffu, mx0, 2));
            mx1 = fmaxf(mx1, __shfl_xor_sync(0xffffffffu, mx1, 1));
            mx1 = fmaxf(mx1, __shfl_xor_sync(0xffffffffu, mx1, 2));

            const float mn0 = fmaxf(m0, mx0);
            const float mn1 = fmaxf(m1, mx1);
            const float al0 = __expf(m0 - mn0);
            const float al1 = __expf(m1 - mn1);
            m0 = mn0; m1 = mn1;

            uint32_t pt[4][4];
            float sum0 = 0.0f, sum1 = 0.0f;
            #pragma unroll
            for (int nt = 0; nt < 4; nt++) {
                float p0 = __expf(s[nt][0] - m0);
                float p1 = __expf(s[nt][1] - m0);
                float p2 = __expf(s[nt][2] - m1);
                float p3 = __expf(s[nt][3] - m1);
                pt[nt][0] = f2tf(p0); pt[nt][1] = f2tf(p1);
                pt[nt][2] = f2tf(p2); pt[nt][3] = f2tf(p3);
                sum0 += __uint_as_float(pt[nt][0]) + __uint_as_float(pt[nt][1]);
                sum1 += __uint_as_float(pt[nt][2]) + __uint_as_float(pt[nt][3]);
            }
            sum0 += __shfl_xor_sync(0xffffffffu, sum0, 1);
            sum0 += __shfl_xor_sync(0xffffffffu, sum0, 2);
            sum1 += __shfl_xor_sync(0xffffffffu, sum1, 1);
            sum1 += __shfl_xor_sync(0xffffffffu, sum1, 2);
            l0 = l0 * al0 + sum0;
            l1 = l1 * al1 + sum1;

            #pragma unroll
            for (int nt = 0; nt < 8; nt++) {
                o[nt][0] *= al0; o[nt][1] *= al0;
                o[nt][2] *= al1; o[nt][3] *= al1;
            }

            #pragma unroll
            for (int ks = 0; ks < 4; ks++) {
                uint32_t p0a = __shfl_sync(0xffffffffu, pt[ks][0], srcA);
                uint32_t p1a = __shfl_sync(0xffffffffu, pt[ks][1], srcA);
                uint32_t p2a = __shfl_sync(0xffffffffu, pt[ks][2], srcA);
                uint32_t p3a = __shfl_sync(0xffffffffu, pt[ks][3], srcA);
                uint32_t p0b = __shfl_sync(0xffffffffu, pt[ks][0], srcB);
                uint32_t p1b = __shfl_sync(0xffffffffu, pt[ks][1], srcB);
                uint32_t p2b = __shfl_sync(0xffffffffu, pt[ks][2], srcB);
                uint32_t p3b = __shfl_sync(0xffffffffu, pt[ks][3], srcB);
                uint32_t a0 = hi ? p1a : p0a;
                uint32_t a1 = hi ? p3a : p2a;
                uint32_t a2 = hi ? p1b : p0b;
                uint32_t a3 = hi ? p3b : p2b;
                const int k = ks * 8 + t4;
                #pragma unroll
                for (int nt = 0; nt < 8; nt++) {
                    const int hs = nt * 8 + g;
                    uint32_t b0 = Vs[st][k][hs];
                    uint32_t b1 = Vs[st][k + 4][hs];
                    mma_tf32(o[nt], a0, a1, a2, a3, b0, b1);
                }
            }
        }
        __syncthreads();
    }

    const float inv0 = 1.0f / l0;
    const float inv1 = 1.0f / l1;
    const int row = q0 + wrow + g;
    uint32_t* Ob = g_attn + (size_t)(b * Sn) * Dn + h * HSn;
    #pragma unroll
    for (int nt = 0; nt < 8; nt++) {
        const int hs = nt * 8 + 2 * t4;
        *(uint2*)&Ob[(size_t)row * Dn + hs] =
            make_uint2(f2tf(o[nt][0] * inv0), f2tf(o[nt][1] * inv0));
        *(uint2*)&Ob[(size_t)(row + 8) * Dn + hs] =
            make_uint2(f2tf(o[nt][2] * inv1), f2tf(o[nt][3] * inv1));
    }
}

// ---------------------------------------------------------------------------
// Kernel 3: output projection (R6 structure, 3 blocks/SM target).
// grid = (D/128, B*S/128), block = 256
// ---------------------------------------------------------------------------
__global__ __launch_bounds__(256, 3) void outproj_tc(
    const float* __restrict__ bo,
    float* __restrict__ out)
{
    const int nt0 = blockIdx.x * 128;
    const int m0 = blockIdx.y * 128;
    const uint32_t* A = g_attn + (size_t)m0 * Dn;

    __shared__ uint32_t As[2][128][20];
    __shared__ uint32_t Bs[2][16][136];

    const int tid = threadIdx.x;
    const int lane = tid & 31;
    const int w = tid >> 5;
    const int wm = w >> 1;
    const int wn = w & 1;
    const int g = lane >> 2;
    const int t4 = lane & 3;

    const int ar = tid >> 1;
    const int ac = (tid & 1) * 8;
    const int bk = tid >> 4;
    const int bn = (tid & 15) * 8;
    const uint32_t* Arow = A + (size_t)ar * Dn + ac;
    const uint32_t* Bsrc = g_wot + nt0 + bn;

    float c[2][8][4] = {};

    cp16(&As[0][ar][ac],     Arow);
    cp16(&As[0][ar][ac + 4], Arow + 4);
    cp16(&Bs[0][bk][bn],     Bsrc + (size_t)bk * Dn);
    cp16(&Bs[0][bk][bn + 4], Bsrc + (size_t)bk * Dn + 4);
    CP_COMMIT();
    CP_WAIT0();
    __syncthreads();

    int buf = 0;
    for (int ch = 0; ch < 64; ch++) {
        const bool more = (ch + 1 < 64);
        if (more) {
            const int kc = (ch + 1) * 16;
            const int nb = buf ^ 1;
            cp16(&As[nb][ar][ac],     Arow + kc);
            cp16(&As[nb][ar][ac + 4], Arow + kc + 4);
            cp16(&Bs[nb][bk][bn],     Bsrc + (size_t)(kc + bk) * Dn);
            cp16(&Bs[nb][bk][bn + 4], Bsrc + (size_t)(kc + bk) * Dn + 4);
            CP_COMMIT();
        }

        #pragma unroll
        for (int ks = 0; ks < 2; ks++) {
            const int k = ks * 8 + t4;
            uint32_t a[2][4];
            #pragma unroll
            for (int mt = 0; mt < 2; mt++) {
                const int r = wm * 32 + mt * 16 + g;
                a[mt][0] = As[buf][r][k];
                a[mt][1] = As[buf][r + 8][k];
                a[mt][2] = As[buf][r][k + 4];
                a[mt][3] = As[buf][r + 8][k + 4];
            }
            #pragma unroll
            for (int nt = 0; nt < 8; nt++) {
                const int n = wn * 64 + nt * 8 + g;
                uint32_t b0 = Bs[buf][k][n];
                uint32_t b1 = Bs[buf][k + 4][n];
                mma_tf32(c[0][nt], a[0][0], a[0][1], a[0][2], a[0][3], b0, b1);
                mma_tf32(c[1][nt], a[1][0], a[1][1], a[1][2], a[1][3], b0, b1);
            }
        }

        if (more) CP_WAIT0();
        __syncthreads();
        buf ^= 1;
    }

    float* C = out + (size_t)m0 * Dn + nt0;
    #pragma unroll
    for (int mt = 0; mt < 2; mt++) {
        const int r = wm * 32 + mt * 16 + g;
        #pragma unroll
        for (int nt = 0; nt < 8; nt++) {
            const int n = wn * 64 + nt * 8 + 2 * t4;
            const float2 bias = *(const float2*)&bo[nt0 + n];
            *(float2*)&C[(size_t)r * Dn + n] =
                make_float2(c[mt][nt][0] + bias.x, c[mt][nt][1] + bias.y);
            *(float2*)&C[(size_t)(r + 8) * Dn + n] =
                make_float2(c[mt][nt][2] + bias.x, c[mt][nt][3] + bias.y);
        }
    }
}

// ---------------------------------------------------------------------------
extern "C" void kernel_launch(void* const* d_in, const int* in_sizes, int n_in,
                              void* d_out, int out_size)
{
    const float* X  = (const float*)d_in[0];
    const float* Wq = (const float*)d_in[1];
    const float* Wk = (const float*)d_in[2];
    const float* Wv = (const float*)d_in[3];
    const float* Wo = (const float*)d_in[4];
    const float* bo = (const float*)d_in[5];
    float* out = (float*)d_out;

    cvt_all<<<2048, 256>>>((const float4*)X, (const float4*)Wq,
                           (const float4*)Wk, (const float4*)Wv,
                           (const float4*)Wo);
    proj_tc<<<dim3(24, (Bn * Sn) / 128), 256>>>();
    attn_tc<<<dim3(Sn / 128, Bn * Hn), 256>>>();
    outproj_tc<<<dim3(Dn / 128, (Bn * Sn) / 128), 256>>>(bo, out);
}

// round 9
// speedup vs baseline: 1.1048x; 1.0024x over previous
#include <cuda_runtime.h>
#include <cstdint>

// Problem constants
constexpr int Bn = 4;
constexpr int Sn = 2048;
constexpr int Dn = 1024;
constexpr int Hn = 16;
constexpr int HSn = 64;     // head size

constexpr int WSZ = Hn * Dn * HSn;         // one projection weight: 1M elems
constexpr int NX4 = Bn * Sn * Dn / 4;
constexpr int NW4 = WSZ / 4;

// Scratch. All hold tf32 BIT PATTERNS (as uint32).
__device__ uint32_t g_q[Bn * Hn * Sn * HSn];
__device__ uint32_t g_k[Bn * Hn * Sn * HSn];
__device__ uint32_t g_v[Bn * Hn * Sn * HSn];
__device__ uint32_t g_attn[Bn * Sn * Dn];
__device__ uint32_t g_xt[Bn * Sn * Dn];
__device__ uint32_t g_wt[3 * WSZ];
__device__ uint32_t g_wot[Dn * Dn];

// ---------------------------------------------------------------------------
// helpers
// ---------------------------------------------------------------------------
__device__ __forceinline__ uint32_t f2tf(float x) {
    uint32_t r;
    asm("cvt.rna.tf32.f32 %0, %1;" : "=r"(r) : "f"(x));
    return r;
}

__device__ __forceinline__ void mma_tf32(float c[4],
                                         uint32_t a0, uint32_t a1, uint32_t a2, uint32_t a3,
                                         uint32_t b0, uint32_t b1) {
    asm volatile(
        "mma.sync.aligned.m16n8k8.row.col.f32.tf32.tf32.f32 "
        "{%0,%1,%2,%3}, {%4,%5,%6,%7}, {%8,%9}, {%0,%1,%2,%3};\n"
        : "+f"(c[0]), "+f"(c[1]), "+f"(c[2]), "+f"(c[3])
        : "r"(a0), "r"(a1), "r"(a2), "r"(a3), "r"(b0), "r"(b1));
}

__device__ __forceinline__ void cp16(void* smem_dst, const void* gmem_src) {
    uint32_t d = (uint32_t)__cvta_generic_to_shared(smem_dst);
    asm volatile("cp.async.ca.shared.global [%0], [%1], 16;\n"
                 :: "r"(d), "l"(gmem_src));
}
#define CP_COMMIT() asm volatile("cp.async.commit_group;\n" ::: "memory")
#define CP_WAIT0()  asm volatile("cp.async.wait_group 0;\n" ::: "memory")
#define CP_WAIT1()  asm volatile("cp.async.wait_group 1;\n" ::: "memory")

// ---------------------------------------------------------------------------
// Kernel 0: fused fp32 -> tf32 conversion of X, Wq, Wk, Wv, Wo
// ---------------------------------------------------------------------------
__global__ __launch_bounds__(256) void cvt_all(
    const float4* __restrict__ X,  const float4* __restrict__ Wq,
    const float4* __restrict__ Wk, const float4* __restrict__ Wv,
    const float4* __restrict__ Wo)
{
    const int total = NX4 + 4 * NW4;
    int i = blockIdx.x * blockDim.x + threadIdx.x;
    const int stride = gridDim.x * blockDim.x;
    for (; i < total; i += stride) {
        const float4* s;
        uint4* d;
        int off;
        if (i < NX4)                { s = X;  d = (uint4*)g_xt;            off = i; }
        else if (i < NX4 + NW4)     { s = Wq; d = (uint4*)g_wt;            off = i - NX4; }
        else if (i < NX4 + 2 * NW4) { s = Wk; d = (uint4*)(g_wt + WSZ);    off = i - NX4 - NW4; }
        else if (i < NX4 + 3 * NW4) { s = Wv; d = (uint4*)(g_wt + 2*WSZ);  off = i - NX4 - 2*NW4; }
        else                        { s = Wo; d = (uint4*)g_wot;           off = i - NX4 - 3*NW4; }
        float4 v = s[off];
        d[off] = make_uint4(f2tf(v.x), f2tf(v.y), f2tf(v.z), f2tf(v.w));
    }
}

// ---------------------------------------------------------------------------
// Kernel 1: merged QKV projection GEMM (R6 structure, 3 blocks/SM target).
// Block tile 128x128 (2 heads). 8 warps (4x2), warp tile 32x64. K chunk 16.
// grid = (24, B*S/128), block = 256
// ---------------------------------------------------------------------------
__global__ __launch_bounds__(256, 3) void proj_tc()
{
    const int xx = blockIdx.x;
    const int which = xx >> 3;
    const int h0 = (xx & 7) * 2;
    const int m0 = blockIdx.y * 128;
    const int b = m0 >> 11;
    const int s0 = m0 & 2047;

    uint32_t* outb = (which == 0) ? g_q : (which == 1) ? g_k : g_v;
    const uint32_t* A = g_xt + (size_t)m0 * Dn;
    const uint32_t* B0 = g_wt + (size_t)which * WSZ + (size_t)h0 * Dn * HSn;

    __shared__ uint32_t As[2][128][20];
    __shared__ uint32_t Bs[2][16][136];

    const int tid = threadIdx.x;
    const int lane = tid & 31;
    const int w = tid >> 5;
    const int wm = w >> 1;
    const int wn = w & 1;
    const int g = lane >> 2;
    const int t4 = lane & 3;

    const int ar = tid >> 1;
    const int ac = (tid & 1) * 8;
    const int bk = tid >> 4;
    const int bn = (tid & 15) * 8;
    const uint32_t* Bsrc = B0 + (bn < 64 ? bn : (size_t)Dn * HSn + (bn - 64));
    const uint32_t* Arow = A + (size_t)ar * Dn + ac;

    float c[2][8][4] = {};

    cp16(&As[0][ar][ac],     Arow);
    cp16(&As[0][ar][ac + 4], Arow + 4);
    cp16(&Bs[0][bk][bn],     Bsrc + bk * HSn);
    cp16(&Bs[0][bk][bn + 4], Bsrc + bk * HSn + 4);
    CP_COMMIT();
    CP_WAIT0();
    __syncthreads();

    int buf = 0;
    for (int ch = 0; ch < 64; ch++) {
        const bool more = (ch + 1 < 64);
        if (more) {
            const int kc = (ch + 1) * 16;
            const int nb = buf ^ 1;
            cp16(&As[nb][ar][ac],     Arow + kc);
            cp16(&As[nb][ar][ac + 4], Arow + kc + 4);
            cp16(&Bs[nb][bk][bn],     Bsrc + (kc + bk) * HSn);
            cp16(&Bs[nb][bk][bn + 4], Bsrc + (kc + bk) * HSn + 4);
            CP_COMMIT();
        }

        #pragma unroll
        for (int ks = 0; ks < 2; ks++) {
            const int k = ks * 8 + t4;
            uint32_t a[2][4];
            #pragma unroll
            for (int mt = 0; mt < 2; mt++) {
                const int r = wm * 32 + mt * 16 + g;
                a[mt][0] = As[buf][r][k];
                a[mt][1] = As[buf][r + 8][k];
                a[mt][2] = As[buf][r][k + 4];
                a[mt][3] = As[buf][r + 8][k + 4];
            }
            #pragma unroll
            for (int nt = 0; nt < 8; nt++) {
                const int n = wn * 64 + nt * 8 + g;
                uint32_t b0 = Bs[buf][k][n];
                uint32_t b1 = Bs[buf][k + 4][n];
                mma_tf32(c[0][nt], a[0][0], a[0][1], a[0][2], a[0][3], b0, b1);
                mma_tf32(c[1][nt], a[1][0], a[1][1], a[1][2], a[1][3], b0, b1);
            }
        }

        if (more) CP_WAIT0();
        __syncthreads();
        buf ^= 1;
    }

    const float sc = (which == 0) ? 0.125f : 1.0f;
    uint32_t* O = outb + ((size_t)(b * Hn + h0 + wn) * Sn + s0) * HSn;
    #pragma unroll
    for (int mt = 0; mt < 2; mt++) {
        const int r = wm * 32 + mt * 16 + g;
        #pragma unroll
        for (int nt = 0; nt < 8; nt++) {
            const int hs = nt * 8 + 2 * t4;
            *(uint2*)&O[(size_t)r * HSn + hs] =
                make_uint2(f2tf(c[mt][nt][0] * sc), f2tf(c[mt][nt][1] * sc));
            *(uint2*)&O[(size_t)(r + 8) * HSn + hs] =
                make_uint2(f2tf(c[mt][nt][2] * sc), f2tf(c[mt][nt][3] * sc));
        }
    }
}

// ---------------------------------------------------------------------------
// Kernel 2: causal flash attention (R6 structure, 2 blocks/SM guaranteed,
// reversed qt order for LPT scheduling). BM=128, BN=32, 8 warps along M.
// grid = (S/128, B*H), block = 256
// ---------------------------------------------------------------------------
__global__ __launch_bounds__(256, 2) void attn_tc()
{
    const int qt = (int)gridDim.x - 1 - (int)blockIdx.x;   // heavy blocks first
    const int bh = blockIdx.y;
    const int b = bh >> 4;
    const int h = bh & 15;
    const int q0 = qt * 128;

    const uint32_t* Q = g_q + (size_t)(bh * Sn + q0) * HSn;
    const uint32_t* K = g_k + (size_t)bh * Sn * HSn;
    const uint32_t* V = g_v + (size_t)bh * Sn * HSn;

    __shared__ uint32_t Ks[2][32][68];
    __shared__ uint32_t Vs[2][32][72];

    const int tid = threadIdx.x;
    const int lane = tid & 31;
    const int w = tid >> 5;
    const int g = lane >> 2;
    const int t4 = lane & 3;
    const int wrow = w * 16;

    uint32_t qf[8][4];
    {
        const uint32_t* Qw = Q + (size_t)(wrow + g) * HSn;
        #pragma unroll
        for (int ks = 0; ks < 8; ks++) {
            const int e = ks * 8 + t4;
            qf[ks][0] = Qw[e];
            qf[ks][1] = Qw[8 * HSn + e];
            qf[ks][2] = Qw[e + 4];
            qf[ks][3] = Qw[8 * HSn + e + 4];
        }
    }

    float o[8][4] = {};
    float m0 = -1e30f, m1 = -1e30f, l0 = 0.0f, l1 = 0.0f;

    const int kn = tid >> 3;
    const int ke = (tid & 7) * 8;
    const int rmax = q0 + wrow + 15;
    const int jmax = 4 * qt + 3;

    const int srcA = (lane & ~3) | (t4 >> 1);
    const int srcB = srcA + 2;
    const bool hi = (t4 & 1) != 0;

    {
        const uint32_t* kp = K + (size_t)kn * HSn + ke;
        const uint32_t* vp = V + (size_t)kn * HSn + ke;
        cp16(&Ks[0][kn][ke], kp);     cp16(&Ks[0][kn][ke + 4], kp + 4);
        cp16(&Vs[0][kn][ke], vp);     cp16(&Vs[0][kn][ke + 4], vp + 4);
        CP_COMMIT();
    }

    for (int j = 0; j <= jmax; j++) {
        const int st = j & 1;
        const int k0 = j * 32;

        if (j < jmax) {
            const int kc = (j + 1) * 32;
            const uint32_t* kp = K + (size_t)(kc + kn) * HSn + ke;
            const uint32_t* vp = V + (size_t)(kc + kn) * HSn + ke;
            cp16(&Ks[st ^ 1][kn][ke], kp);  cp16(&Ks[st ^ 1][kn][ke + 4], kp + 4);
            cp16(&Vs[st ^ 1][kn][ke], vp);  cp16(&Vs[st ^ 1][kn][ke + 4], vp + 4);
            CP_COMMIT();
            CP_WAIT1();
        } else {
            CP_WAIT0();
        }
        __syncthreads();

        if (k0 <= rmax) {
            float s[4][4] = {};
            #pragma unroll
            for (int ks = 0; ks < 8; ks++) {
                const int e = ks * 8 + t4;
                #pragma unroll
                for (int nt = 0; nt < 4; nt++) {
                    const int n = nt * 8 + g;
                    uint32_t b0 = Ks[st][n][e];
                    uint32_t b1 = Ks[st][n][e + 4];
                    mma_tf32(s[nt], qf[ks][0], qf[ks][1], qf[ks][2], qf[ks][3], b0, b1);
                }
            }

            const int r0g = q0 + wrow + g;
            const int r1g = r0g + 8;
            #pragma unroll
            for (int nt = 0; nt < 4; nt++) {
                const int kc0 = k0 + nt * 8 + 2 * t4;
                if (kc0 > r0g)     s[nt][0] = -1e30f;
                if (kc0 + 1 > r0g) s[nt][1] = -1e30f;
                if (kc0 > r1g)     s[nt][2] = -1e30f;
                if (kc0 + 1 > r1g) s[nt][3] = -1e30f;
            }

            float mx0 = -1e30f, mx1 = -1e30f;
            #pragma unroll
            for (int nt = 0; nt < 4; nt++) {
                mx0 = fmaxf(mx0, fmaxf(s[nt][0], s[nt][1]));
                mx1 = fmaxf(mx1, fmaxf(s[nt][2], s[nt][3]));
            }
            mx0 = fmaxf(mx0, __shfl_xor_sync(0xffffffffu, mx0, 1));
            mx0 = fmaxf(mx0, __shfl_xor_sync(0xffffffffu, mx0, 2));
            mx1 = fmaxf(mx1, __shfl_xor_sync(0xffffffffu, mx1, 1));
            mx1 = fmaxf(mx1, __shfl_xor_sync(0xffffffffu, mx1, 2));

            const float mn0 = fmaxf(m0, mx0);
            const float mn1 = fmaxf(m1, mx1);
            const float al0 = __expf(m0 - mn0);
            const float al1 = __expf(m1 - mn1);
            m0 = mn0; m1 = mn1;

            uint32_t pt[4][4];
            float sum0 = 0.0f, sum1 = 0.0f;
            #pragma unroll
            for (int nt = 0; nt < 4; nt++) {
                float p0 = __expf(s[nt][0] - m0);
                float p1 = __expf(s[nt][1] - m0);
                float p2 = __expf(s[nt][2] - m1);
                float p3 = __expf(s[nt][3] - m1);
                pt[nt][0] = f2tf(p0); pt[nt][1] = f2tf(p1);
                pt[nt][2] = f2tf(p2); pt[nt][3] = f2tf(p3);
                sum0 += __uint_as_float(pt[nt][0]) + __uint_as_float(pt[nt][1]);
                sum1 += __uint_as_float(pt[nt][2]) + __uint_as_float(pt[nt][3]);
            }
            sum0 += __shfl_xor_sync(0xffffffffu, sum0, 1);
            sum0 += __shfl_xor_sync(0xffffffffu, sum0, 2);
            sum1 += __shfl_xor_sync(0xffffffffu, sum1, 1);
            sum1 += __shfl_xor_sync(0xffffffffu, sum1, 2);
            l0 = l0 * al0 + sum0;
            l1 = l1 * al1 + sum1;

            #pragma unroll
            for (int nt = 0; nt < 8; nt++) {
                o[nt][0] *= al0; o[nt][1] *= al0;
                o[nt][2] *= al1; o[nt][3] *= al1;
            }

            #pragma unroll
            for (int ks = 0; ks < 4; ks++) {
                uint32_t p0a = __shfl_sync(0xffffffffu, pt[ks][0], srcA);
                uint32_t p1a = __shfl_sync(0xffffffffu, pt[ks][1], srcA);
                uint32_t p2a = __shfl_sync(0xffffffffu, pt[ks][2], srcA);
                uint32_t p3a = __shfl_sync(0xffffffffu, pt[ks][3], srcA);
                uint32_t p0b = __shfl_sync(0xffffffffu, pt[ks][0], srcB);
                uint32_t p1b = __shfl_sync(0xffffffffu, pt[ks][1], srcB);
                uint32_t p2b = __shfl_sync(0xffffffffu, pt[ks][2], srcB);
                uint32_t p3b = __shfl_sync(0xffffffffu, pt[ks][3], srcB);
                uint32_t a0 = hi ? p1a : p0a;
                uint32_t a1 = hi ? p3a : p2a;
                uint32_t a2 = hi ? p1b : p0b;
                uint32_t a3 = hi ? p3b : p2b;
                const int k = ks * 8 + t4;
                #pragma unroll
                for (int nt = 0; nt < 8; nt++) {
                    const int hs = nt * 8 + g;
                    uint32_t b0 = Vs[st][k][hs];
                    uint32_t b1 = Vs[st][k + 4][hs];
                    mma_tf32(o[nt], a0, a1, a2, a3, b0, b1);
                }
            }
        }
        __syncthreads();
    }

    const float inv0 = 1.0f / l0;
    const float inv1 = 1.0f / l1;
    const int row = q0 + wrow + g;
    uint32_t* Ob = g_attn + (size_t)(b * Sn) * Dn + h * HSn;
    #pragma unroll
    for (int nt = 0; nt < 8; nt++) {
        const int hs = nt * 8 + 2 * t4;
        *(uint2*)&Ob[(size_t)row * Dn + hs] =
            make_uint2(f2tf(o[nt][0] * inv0), f2tf(o[nt][1] * inv0));
        *(uint2*)&Ob[(size_t)(row + 8) * Dn + hs] =
            make_uint2(f2tf(o[nt][2] * inv1), f2tf(o[nt][3] * inv1));
    }
}

// ---------------------------------------------------------------------------
// Kernel 3: output projection (R6 structure, 3 blocks/SM target).
// grid = (D/128, B*S/128), block = 256
// ---------------------------------------------------------------------------
__global__ __launch_bounds__(256, 3) void outproj_tc(
    const float* __restrict__ bo,
    float* __restrict__ out)
{
    const int nt0 = blockIdx.x * 128;
    const int m0 = blockIdx.y * 128;
    const uint32_t* A = g_attn + (size_t)m0 * Dn;

    __shared__ uint32_t As[2][128][20];
    __shared__ uint32_t Bs[2][16][136];

    const int tid = threadIdx.x;
    const int lane = tid & 31;
    const int w = tid >> 5;
    const int wm = w >> 1;
    const int wn = w & 1;
    const int g = lane >> 2;
    const int t4 = lane & 3;

    const int ar = tid >> 1;
    const int ac = (tid & 1) * 8;
    const int bk = tid >> 4;
    const int bn = (tid & 15) * 8;
    const uint32_t* Arow = A + (size_t)ar * Dn + ac;
    const uint32_t* Bsrc = g_wot + nt0 + bn;

    float c[2][8][4] = {};

    cp16(&As[0][ar][ac],     Arow);
    cp16(&As[0][ar][ac + 4], Arow + 4);
    cp16(&Bs[0][bk][bn],     Bsrc + (size_t)bk * Dn);
    cp16(&Bs[0][bk][bn + 4], Bsrc + (size_t)bk * Dn + 4);
    CP_COMMIT();
    CP_WAIT0();
    __syncthreads();

    int buf = 0;
    for (int ch = 0; ch < 64; ch++) {
        const bool more = (ch + 1 < 64);
        if (more) {
            const int kc = (ch + 1) * 16;
            const int nb = buf ^ 1;
            cp16(&As[nb][ar][ac],     Arow + kc);
            cp16(&As[nb][ar][ac + 4], Arow + kc + 4);
            cp16(&Bs[nb][bk][bn],     Bsrc + (size_t)(kc + bk) * Dn);
            cp16(&Bs[nb][bk][bn + 4], Bsrc + (size_t)(kc + bk) * Dn + 4);
            CP_COMMIT();
        }

        #pragma unroll
        for (int ks = 0; ks < 2; ks++) {
            const int k = ks * 8 + t4;
            uint32_t a[2][4];
            #pragma unroll
            for (int mt = 0; mt < 2; mt++) {
                const int r = wm * 32 + mt * 16 + g;
                a[mt][0] = As[buf][r][k];
                a[mt][1] = As[buf][r + 8][k];
                a[mt][2] = As[buf][r][k + 4];
                a[mt][3] = As[buf][r + 8][k + 4];
            }
            #pragma unroll
            for (int nt = 0; nt < 8; nt++) {
                const int n = wn * 64 + nt * 8 + g;
                uint32_t b0 = Bs[buf][k][n];
                uint32_t b1 = Bs[buf][k + 4][n];
                mma_tf32(c[0][nt], a[0][0], a[0][1], a[0][2], a[0][3], b0, b1);
                mma_tf32(c[1][nt], a[1][0], a[1][1], a[1][2], a[1][3], b0, b1);
            }
        }

        if (more) CP_WAIT0();
        __syncthreads();
        buf ^= 1;
    }

    float* C = out + (size_t)m0 * Dn + nt0;
    #pragma unroll
    for (int mt = 0; mt < 2; mt++) {
        const int r = wm * 32 + mt * 16 + g;
        #pragma unroll
        for (int nt = 0; nt < 8; nt++) {
            const int n = wn * 64 + nt * 8 + 2 * t4;
            const float2 bias = *(const float2*)&bo[nt0 + n];
            *(float2*)&C[(size_t)r * Dn + n] =
                make_float2(c[mt][nt][0] + bias.x, c[mt][nt][1] + bias.y);
            *(float2*)&C[(size_t)(r + 8) * Dn + n] =
                make_float2(c[mt][nt][2] + bias.x, c[mt][nt][3] + bias.y);
        }
    }
}

// ---------------------------------------------------------------------------
extern "C" void kernel_launch(void* const* d_in, const int* in_sizes, int n_in,
                              void* d_out, int out_size)
{
    const float* X  = (const float*)d_in[0];
    const float* Wq = (const float*)d_in[1];
    const float* Wk = (const float*)d_in[2];
    const float* Wv = (const float*)d_in[3];
    const float* Wo = (const float*)d_in[4];
    const float* bo = (const float*)d_in[5];
    float* out = (float*)d_out;

    cvt_all<<<2048, 256>>>((const float4*)X, (const float4*)Wq,
                           (const float4*)Wk, (const float4*)Wv,
                           (const float4*)Wo);
    proj_tc<<<dim3(24, (Bn * Sn) / 128), 256>>>();
    attn_tc<<<dim3(Sn / 128, Bn * Hn), 256>>>();
    outproj_tc<<<dim3(Dn / 128, (Bn * Sn) / 128), 256>>>(bo, out);
}

// round 11
// speedup vs baseline: 1.3931x; 1.2609x over previous
#include <cuda_runtime.h>
#include <cstdint>

constexpr int Bn = 4, Sn = 2048, Dn = 1024, Hn = 16, HSn = 64;

// Scratch (tf32 bit patterns)
__device__ uint32_t g_q[Bn * Hn * Sn * HSn];
__device__ uint32_t g_k[Bn * Hn * Sn * HSn];
__device__ uint32_t g_v[Bn * Hn * Sn * HSn];
__device__ uint32_t g_attn[Bn * Sn * Dn];
__device__ uint32_t g_wot[Dn * Dn];              // Wo tf32 (row-major, outproj B)
// Fragment-ordered operands for proj:
//   g_xt2[mblk 64][kchunk 64][frag 16][lane 32] (uint4) frag = ((wm*2+mt)*2+ks)
//   g_wt2[blk 24][kchunk 64][frag 16][lane 32]  (uint4) frag = (wn*8+nt)
__device__ uint4 g_xt2[64 * 64 * 512];
__device__ uint4 g_wt2[24 * 64 * 512];

__device__ __forceinline__ uint32_t f2tf(float x) {
    uint32_t r; asm("cvt.rna.tf32.f32 %0, %1;" : "=r"(r) : "f"(x)); return r;
}
__device__ __forceinline__ void mma_tf32(float c[4], uint32_t a0, uint32_t a1,
                                         uint32_t a2, uint32_t a3, uint32_t b0, uint32_t b1) {
    asm volatile("mma.sync.aligned.m16n8k8.row.col.f32.tf32.tf32.f32 "
        "{%0,%1,%2,%3}, {%4,%5,%6,%7}, {%8,%9}, {%0,%1,%2,%3};\n"
        : "+f"(c[0]), "+f"(c[1]), "+f"(c[2]), "+f"(c[3])
        : "r"(a0), "r"(a1), "r"(a2), "r"(a3), "r"(b0), "r"(b1));
}
__device__ __forceinline__ void cp16(void* s, const void* g) {
    uint32_t d = (uint32_t)__cvta_generic_to_shared(s);
    asm volatile("cp.async.ca.shared.global [%0], [%1], 16;\n" :: "r"(d), "l"(g));
}
#define CP_COMMIT() asm volatile("cp.async.commit_group;\n" ::: "memory")
#define CP_WAIT0()  asm volatile("cp.async.wait_group 0;\n" ::: "memory")
#define CP_WAIT1()  asm volatile("cp.async.wait_group 1;\n" ::: "memory")

// ---------------------------------------------------------------------------
// Kernel 0a: X -> fragment-ordered tf32 (g_xt2)
// uint4 index i: lane=i&31, frag=(i>>5)&15 {ks=f&1, mt=(f>>1)&1, wm=f>>2},
// kc=(i>>9)&63, mblk=i>>15.
// words: (A[r0][k0], A[r0+8][k0], A[r0][k0+4], A[r0+8][k0+4])
// ---------------------------------------------------------------------------
__global__ __launch_bounds__(256) void cvt_x2(const float* __restrict__ X)
{
    const int total = 64 * 64 * 512;
    int i = blockIdx.x * blockDim.x + threadIdx.x;
    for (; i < total; i += gridDim.x * blockDim.x) {
        const int lane = i & 31;
        const int frag = (i >> 5) & 15;
        const int kc = (i >> 9) & 63;
        const int mblk = i >> 15;
        const int ks = frag & 1, mt = (frag >> 1) & 1, wm = frag >> 2;
        const int g = lane >> 2, t4 = lane & 3;
        const int r0 = mblk * 128 + wm * 32 + mt * 16 + g;
        const int k0 = kc * 16 + ks * 8 + t4;
        const float* p = X + (size_t)r0 * Dn + k0;
        uint4 v;
        v.x = f2tf(p[0]);
        v.y = f2tf(p[8 * Dn]);
        v.z = f2tf(p[4]);
        v.w = f2tf(p[8 * Dn + 4]);
        g_xt2[i] = v;
    }
}

// ---------------------------------------------------------------------------
// Kernel 0b: QKV weights -> fragment-ordered tf32 (g_wt2)
// uint4 index i: lane=i&31, frag=(i>>5)&15 {nt=f&7, wn=f>>3}, kc=(i>>9)&63,
// blk=i>>15 {which=blk>>3, nb=blk&7}. n_local = wn*64+nt*8+g;
// head = nb*2 + (n_local>=64); e = n_local&63.
// words k offsets: t4, t4+4, 8+t4, 12+t4  (ks0 b0/b1, ks1 b0/b1)
// ---------------------------------------------------------------------------
__global__ __launch_bounds__(256) void cvt_w2(
    const float* __restrict__ Wq, const float* __restrict__ Wk,
    const float* __restrict__ Wv)
{
    const int total = 24 * 64 * 512;
    int i = blockIdx.x * blockDim.x + threadIdx.x;
    for (; i < total; i += gridDim.x * blockDim.x) {
        const int lane = i & 31;
        const int frag = (i >> 5) & 15;
        const int kc = (i >> 9) & 63;
        const int blk = i >> 15;
        const int which = blk >> 3, nb = blk & 7;
        const int nt = frag & 7, wn = frag >> 3;
        const int g = lane >> 2, t4 = lane & 3;
        const int n_local = wn * 64 + nt * 8 + g;
        const int head = nb * 2 + (n_local >= 64 ? 1 : 0);
        const int e = n_local & 63;
        const float* W = (which == 0) ? Wq : (which == 1) ? Wk : Wv;
        const float* p = W + ((size_t)head * Dn + kc * 16) * HSn + e;
        uint4 v;
        v.x = f2tf(p[(size_t)(t4) * HSn]);
        v.y = f2tf(p[(size_t)(t4 + 4) * HSn]);
        v.z = f2tf(p[(size_t)(8 + t4) * HSn]);
        v.w = f2tf(p[(size_t)(12 + t4) * HSn]);
        g_wt2[i] = v;
    }
}

// Kernel 0c: Wo -> tf32 (row-major, for outproj)
__global__ __launch_bounds__(256) void cvt_wo(const float4* __restrict__ Wo)
{
    const int n4 = Dn * Dn / 4;
    int i = blockIdx.x * blockDim.x + threadIdx.x;
    for (; i < n4; i += gridDim.x * blockDim.x) {
        float4 v = Wo[i];
        ((uint4*)g_wot)[i] = make_uint4(f2tf(v.x), f2tf(v.y), f2tf(v.z), f2tf(v.w));
    }
}

// ---------------------------------------------------------------------------
// Kernel 1: merged QKV projection, fragment-ordered smem, LDS.128 frag loads.
// Block tile 128x128 (2 heads), 8 warps (4x2), warp tile 32x64, K chunk 16,
// 2-stage cp.async. grid = (24, 64), block 256.
// ---------------------------------------------------------------------------
__global__ __launch_bounds__(256) void proj_tc()
{
    const int xx = blockIdx.x;           // 0..23
    const int which = xx >> 3;
    const int nb = xx & 7;
    const int mblk = blockIdx.y;         // 0..63
    const int m0 = mblk * 128;
    const int b = m0 >> 11;
    const int s0 = m0 & 2047;

    uint32_t* outb = (which == 0) ? g_q : (which == 1) ? g_k : g_v;
    const uint4* Asrc = g_xt2 + (size_t)mblk * 64 * 512;
    const uint4* Bsrc = g_wt2 + (size_t)xx * 64 * 512;

    __shared__ uint4 As4[2][512];
    __shared__ uint4 Bs4[2][512];

    const int tid = threadIdx.x;
    const int lane = tid & 31;
    const int w = tid >> 5;
    const int wm = w >> 1;      // 0..3
    const int wn = w & 1;       // 0..1
    const int g = lane >> 2;
    const int t4 = lane & 3;

    float c[2][8][4] = {};

    // prime stage 0 with chunk 0
    {
        const uint4* as = Asrc;
        const uint4* bs = Bsrc;
        cp16(&As4[0][tid],       as + tid);
        cp16(&As4[0][tid + 256], as + tid + 256);
        cp16(&Bs4[0][tid],       bs + tid);
        cp16(&Bs4[0][tid + 256], bs + tid + 256);
        CP_COMMIT();
    }
    CP_WAIT0();
    __syncthreads();

    int buf = 0;
    for (int ch = 0; ch < 64; ch++) {
        const bool more = (ch + 1 < 64);
        if (more) {
            const uint4* as = Asrc + (size_t)(ch + 1) * 512;
            const uint4* bs = Bsrc + (size_t)(ch + 1) * 512;
            const int nbuf = buf ^ 1;
            cp16(&As4[nbuf][tid],       as + tid);
            cp16(&As4[nbuf][tid + 256], as + tid + 256);
            cp16(&Bs4[nbuf][tid],       bs + tid);
            cp16(&Bs4[nbuf][tid + 256], bs + tid + 256);
            CP_COMMIT();
        }

        // A fragments: 4 LDS.128 (2 mtiles x 2 ksteps)
        uint4 af[2][2];
        #pragma unroll
        for (int mt = 0; mt < 2; mt++)
            #pragma unroll
            for (int ks = 0; ks < 2; ks++)
                af[mt][ks] = As4[buf][(((wm * 2 + mt) * 2) + ks) * 32 + lane];

        // B fragments + MMAs: 8 LDS.128, 32 MMA
        #pragma unroll
        for (int nt = 0; nt < 8; nt++) {
            uint4 bf = Bs4[buf][(wn * 8 + nt) * 32 + lane];
            mma_tf32(c[0][nt], af[0][0].x, af[0][0].y, af[0][0].z, af[0][0].w, bf.x, bf.y);
            mma_tf32(c[1][nt], af[1][0].x, af[1][0].y, af[1][0].z, af[1][0].w, bf.x, bf.y);
            mma_tf32(c[0][nt], af[0][1].x, af[0][1].y, af[0][1].z, af[0][1].w, bf.z, bf.w);
            mma_tf32(c[1][nt], af[1][1].x, af[1][1].y, af[1][1].z, af[1][1].w, bf.z, bf.w);
        }

        if (more) CP_WAIT0();
        __syncthreads();
        buf ^= 1;
    }

    // epilogue: head = nb*2 + wn; Q pre-scaled by 0.125; tf32-rounded bits
    const float sc = (which == 0) ? 0.125f : 1.0f;
    const int h0 = nb * 2;
    uint32_t* O = outb + ((size_t)(b * Hn + h0 + wn) * Sn + s0) * HSn;
    #pragma unroll
    for (int mt = 0; mt < 2; mt++) {
        const int r = wm * 32 + mt * 16 + g;
        #pragma unroll
        for (int nt = 0; nt < 8; nt++) {
            const int hs = nt * 8 + 2 * t4;
            *(uint2*)&O[(size_t)r * HSn + hs] =
                make_uint2(f2tf(c[mt][nt][0] * sc), f2tf(c[mt][nt][1] * sc));
            *(uint2*)&O[(size_t)(r + 8) * HSn + hs] =
                make_uint2(f2tf(c[mt][nt][2] * sc), f2tf(c[mt][nt][3] * sc));
        }
    }
}

// ---------------------------------------------------------------------------
// Kernel 2: causal flash attention (R6-exact). grid (16, 64), block 256.
// ---------------------------------------------------------------------------
__global__ __launch_bounds__(256) void attn_tc()
{
    const int qt = blockIdx.x, bh = blockIdx.y;
    const int b = bh >> 4, h = bh & 15, q0 = qt * 128;
    const uint32_t* Q = g_q + (size_t)(bh * Sn + q0) * HSn;
    const uint32_t* K = g_k + (size_t)bh * Sn * HSn;
    const uint32_t* V = g_v + (size_t)bh * Sn * HSn;

    __shared__ uint32_t Ks[2][32][68];
    __shared__ uint32_t Vs[2][32][72];

    const int tid = threadIdx.x, lane = tid & 31, w = tid >> 5;
    const int g = lane >> 2, t4 = lane & 3, wrow = w * 16;

    uint32_t qf[8][4];
    {
        const uint32_t* Qw = Q + (size_t)(wrow + g) * HSn;
        #pragma unroll
        for (int ks = 0; ks < 8; ks++) {
            const int e = ks * 8 + t4;
            qf[ks][0] = Qw[e];           qf[ks][1] = Qw[8 * HSn + e];
            qf[ks][2] = Qw[e + 4];       qf[ks][3] = Qw[8 * HSn + e + 4];
        }
    }
    float o[8][4] = {};
    float m0 = -1e30f, m1 = -1e30f, l0 = 0.0f, l1 = 0.0f;
    const int kn = tid >> 3, ke = (tid & 7) * 8;
    const int rmax = q0 + wrow + 15, jmax = 4 * qt + 3;
    const int srcA = (lane & ~3) | (t4 >> 1), srcB = srcA + 2;
    const bool hi = (t4 & 1) != 0;

    {
        const uint32_t* kp = K + (size_t)kn * HSn + ke;
        const uint32_t* vp = V + (size_t)kn * HSn + ke;
        cp16(&Ks[0][kn][ke], kp); cp16(&Ks[0][kn][ke + 4], kp + 4);
        cp16(&Vs[0][kn][ke], vp); cp16(&Vs[0][kn][ke + 4], vp + 4);
        CP_COMMIT();
    }
    for (int j = 0; j <= jmax; j++) {
        const int st = j & 1, k0 = j * 32;
        if (j < jmax) {
            const int kc = (j + 1) * 32;
            const uint32_t* kp = K + (size_t)(kc + kn) * HSn + ke;
            const uint32_t* vp = V + (size_t)(kc + kn) * HSn + ke;
            cp16(&Ks[st ^ 1][kn][ke], kp); cp16(&Ks[st ^ 1][kn][ke + 4], kp + 4);
            cp16(&Vs[st ^ 1][kn][ke], vp); cp16(&Vs[st ^ 1][kn][ke + 4], vp + 4);
            CP_COMMIT(); CP_WAIT1();
        } else { CP_WAIT0(); }
        __syncthreads();

        if (k0 <= rmax) {
            float s[4][4] = {};
            #pragma unroll
            for (int ks = 0; ks < 8; ks++) {
                const int e = ks * 8 + t4;
                #pragma unroll
                for (int nt = 0; nt < 4; nt++) {
                    const int n = nt * 8 + g;
                    mma_tf32(s[nt], qf[ks][0], qf[ks][1], qf[ks][2], qf[ks][3],
                             Ks[st][n][e], Ks[st][n][e + 4]);
                }
            }
            const int r0g = q0 + wrow + g, r1g = r0g + 8;
            #pragma unroll
            for (int nt = 0; nt < 4; nt++) {
                const int kc0 = k0 + nt * 8 + 2 * t4;
                if (kc0 > r0g)     s[nt][0] = -1e30f;
                if (kc0 + 1 > r0g) s[nt][1] = -1e30f;
                if (kc0 > r1g)     s[nt][2] = -1e30f;
                if (kc0 + 1 > r1g) s[nt][3] = -1e30f;
            }
            float mx0 = -1e30f, mx1 = -1e30f;
            #pragma unroll
            for (int nt = 0; nt < 4; nt++) {
                mx0 = fmaxf(mx0, fmaxf(s[nt][0], s[nt][1]));
                mx1 = fmaxf(mx1, fmaxf(s[nt][2], s[nt][3]));
            }
            mx0 = fmaxf(mx0, __shfl_xor_sync(~0u, mx0, 1));
            mx0 = fmaxf(mx0, __shfl_xor_sync(~0u, mx0, 2));
            mx1 = fmaxf(mx1, __shfl_xor_sync(~0u, mx1, 1));
            mx1 = fmaxf(mx1, __shfl_xor_sync(~0u, mx1, 2));
            const float mn0 = fmaxf(m0, mx0), mn1 = fmaxf(m1, mx1);
            const float al0 = __expf(m0 - mn0), al1 = __expf(m1 - mn1);
            m0 = mn0; m1 = mn1;

            uint32_t pt[4][4];
            float sum0 = 0.0f, sum1 = 0.0f;
            #pragma unroll
            for (int nt = 0; nt < 4; nt++) {
                float p0 = __expf(s[nt][0] - m0), p1 = __expf(s[nt][1] - m0);
                float p2 = __expf(s[nt][2] - m1), p3 = __expf(s[nt][3] - m1);
                pt[nt][0] = f2tf(p0); pt[nt][1] = f2tf(p1);
                pt[nt][2] = f2tf(p2); pt[nt][3] = f2tf(p3);
                sum0 += __uint_as_float(pt[nt][0]) + __uint_as_float(pt[nt][1]);
                sum1 += __uint_as_float(pt[nt][2]) + __uint_as_float(pt[nt][3]);
            }
            sum0 += __shfl_xor_sync(~0u, sum0, 1); sum0 += __shfl_xor_sync(~0u, sum0, 2);
            sum1 += __shfl_xor_sync(~0u, sum1, 1); sum1 += __shfl_xor_sync(~0u, sum1, 2);
            l0 = l0 * al0 + sum0; l1 = l1 * al1 + sum1;

            #pragma unroll
            for (int nt = 0; nt < 8; nt++) {
                o[nt][0] *= al0; o[nt][1] *= al0;
                o[nt][2] *= al1; o[nt][3] *= al1;
            }
            #pragma unroll
            for (int ks = 0; ks < 4; ks++) {
                uint32_t p0a = __shfl_sync(~0u, pt[ks][0], srcA);
                uint32_t p1a = __shfl_sync(~0u, pt[ks][1], srcA);
                uint32_t p2a = __shfl_sync(~0u, pt[ks][2], srcA);
                uint32_t p3a = __shfl_sync(~0u, pt[ks][3], srcA);
                uint32_t p0b = __shfl_sync(~0u, pt[ks][0], srcB);
                uint32_t p1b = __shfl_sync(~0u, pt[ks][1], srcB);
                uint32_t p2b = __shfl_sync(~0u, pt[ks][2], srcB);
                uint32_t p3b = __shfl_sync(~0u, pt[ks][3], srcB);
                uint32_t a0 = hi ? p1a : p0a, a1 = hi ? p3a : p2a;
                uint32_t a2 = hi ? p1b : p0b, a3 = hi ? p3b : p2b;
                const int k = ks * 8 + t4;
                #pragma unroll
                for (int nt = 0; nt < 8; nt++) {
                    const int hs = nt * 8 + g;
                    mma_tf32(o[nt], a0, a1, a2, a3, Vs[st][k][hs], Vs[st][k + 4][hs]);
                }
            }
        }
        __syncthreads();
    }
    const float inv0 = 1.0f / l0, inv1 = 1.0f / l1;
    const int row = q0 + wrow + g;
    uint32_t* Ob = g_attn + (size_t)(b * Sn) * Dn + h * HSn;
    #pragma unroll
    for (int nt = 0; nt < 8; nt++) {
        const int hs = nt * 8 + 2 * t4;
        *(uint2*)&Ob[(size_t)row * Dn + hs] =
            make_uint2(f2tf(o[nt][0] * inv0), f2tf(o[nt][1] * inv0));
        *(uint2*)&Ob[(size_t)(row + 8) * Dn + hs] =
            make_uint2(f2tf(o[nt][2] * inv1), f2tf(o[nt][3] * inv1));
    }
}

// ---------------------------------------------------------------------------
// Kernel 3: output projection (R6-exact). grid (8, 64), block 256.
// ---------------------------------------------------------------------------
__global__ __launch_bounds__(256) void outproj_tc(
    const float* __restrict__ bo, float* __restrict__ out)
{
    const int nt0 = blockIdx.x * 128;
    const int m0 = blockIdx.y * 128;
    const uint32_t* A = g_attn + (size_t)m0 * Dn;

    __shared__ uint32_t As[2][128][20];
    __shared__ uint32_t Bs[2][16][136];

    const int tid = threadIdx.x, lane = tid & 31, w = tid >> 5;
    const int wm = w >> 1, wn = w & 1;
    const int g = lane >> 2, t4 = lane & 3;

    const int ar = tid >> 1, ac = (tid & 1) * 8;
    const int bk = tid >> 4, bn = (tid & 15) * 8;
    const uint32_t* Arow = A + (size_t)ar * Dn + ac;
    const uint32_t* Bsrc = g_wot + nt0 + bn;

    float c[2][8][4] = {};

    cp16(&As[0][ar][ac],     Arow);
    cp16(&As[0][ar][ac + 4], Arow + 4);
    cp16(&Bs[0][bk][bn],     Bsrc + (size_t)bk * Dn);
    cp16(&Bs[0][bk][bn + 4], Bsrc + (size_t)bk * Dn + 4);
    CP_COMMIT();
    CP_WAIT0();
    __syncthreads();

    int buf = 0;
    for (int ch = 0; ch < 64; ch++) {
        const bool more = (ch + 1 < 64);
        if (more) {
            const int kc = (ch + 1) * 16;
            const int nbuf = buf ^ 1;
            cp16(&As[nbuf][ar][ac],     Arow + kc);
            cp16(&As[nbuf][ar][ac + 4], Arow + kc + 4);
            cp16(&Bs[nbuf][bk][bn],     Bsrc + (size_t)(kc + bk) * Dn);
            cp16(&Bs[nbuf][bk][bn + 4], Bsrc + (size_t)(kc + bk) * Dn + 4);
            CP_COMMIT();
        }

        #pragma unroll
        for (int ks = 0; ks < 2; ks++) {
            const int k = ks * 8 + t4;
            uint32_t a[2][4];
            #pragma unroll
            for (int mt = 0; mt < 2; mt++) {
                const int r = wm * 32 + mt * 16 + g;
                a[mt][0] = As[buf][r][k];
                a[mt][1] = As[buf][r + 8][k];
                a[mt][2] = As[buf][r][k + 4];
                a[mt][3] = As[buf][r + 8][k + 4];
            }
            #pragma unroll
            for (int nt = 0; nt < 8; nt++) {
                const int n = wn * 64 + nt * 8 + g;
                uint32_t b0 = Bs[buf][k][n];
                uint32_t b1 = Bs[buf][k + 4][n];
                mma_tf32(c[0][nt], a[0][0], a[0][1], a[0][2], a[0][3], b0, b1);
                mma_tf32(c[1][nt], a[1][0], a[1][1], a[1][2], a[1][3], b0, b1);
            }
        }

        if (more) CP_WAIT0();
        __syncthreads();
        buf ^= 1;
    }

    float* C = out + (size_t)m0 * Dn + nt0;
    #pragma unroll
    for (int mt = 0; mt < 2; mt++) {
        const int r = wm * 32 + mt * 16 + g;
        #pragma unroll
        for (int nt = 0; nt < 8; nt++) {
            const int n = wn * 64 + nt * 8 + 2 * t4;
            const float2 bias = *(const float2*)&bo[nt0 + n];
            *(float2*)&C[(size_t)r * Dn + n] =
                make_float2(c[mt][nt][0] + bias.x, c[mt][nt][1] + bias.y);
            *(float2*)&C[(size_t)(r + 8) * Dn + n] =
                make_float2(c[mt][nt][2] + bias.x, c[mt][nt][3] + bias.y);
        }
    }
}

// ---------------------------------------------------------------------------
extern "C" void kernel_launch(void* const* d_in, const int* in_sizes, int n_in,
                              void* d_out, int out_size)
{
    const float* X  = (const float*)d_in[0];
    const float* Wq = (const float*)d_in[1];
    const float* Wk = (const float*)d_in[2];
    const float* Wv = (const float*)d_in[3];
    const float* Wo = (const float*)d_in[4];
    const float* bo = (const float*)d_in[5];
    float* out = (float*)d_out;

    cvt_x2<<<2048, 256>>>(X);
    cvt_w2<<<1024, 256>>>(Wq, Wk, Wv);
    cvt_wo<<<512, 256>>>((const float4*)Wo);
    proj_tc<<<dim3(24, 64), 256>>>();
    attn_tc<<<dim3(16, 64), 256>>>();
    outproj_tc<<<dim3(8, 64), 256>>>(bo, out);
}

// round 12
// speedup vs baseline: 1.4791x; 1.0617x over previous
#include <cuda_runtime.h>
#include <cstdint>

constexpr int Bn = 4, Sn = 2048, Dn = 1024, Hn = 16, HSn = 64;

// Scratch (tf32 bit patterns)
__device__ uint32_t g_q[Bn * Hn * Sn * HSn];
__device__ uint32_t g_k[Bn * Hn * Sn * HSn];
__device__ uint32_t g_v[Bn * Hn * Sn * HSn];
__device__ uint32_t g_attn[Bn * Sn * Dn];
// Fragment-ordered operand buffers:
//  g_xt2 [mblk 64][kchunk 64][frag16][lane32]  A-frags of X        (proj)
//  g_wt2 [blk 24][kchunk 64][frag16][lane32]   B-frags of Wq/k/v   (proj)
//  g_at2 [mblk 64][kchunk 64][frag16][lane32]  A-frags of attn out (outproj)
//  g_wo2 [nblk 8][kchunk 64][frag16][lane32]   B-frags of Wo       (outproj)
//  g_kf  [bh 64][jt 64][frag16][lane32]        B-frags of K        (attn S)
//  g_vf  [bh 64][jt 64][frag16][lane32]        B-frags of V        (attn PV)
__device__ uint4 g_xt2[64 * 64 * 512];
__device__ uint4 g_wt2[24 * 64 * 512];
__device__ uint4 g_at2[64 * 64 * 512];
__device__ uint4 g_wo2[8 * 64 * 512];
__device__ uint4 g_kf[64 * 64 * 512];
__device__ uint4 g_vf[64 * 64 * 512];

__device__ __forceinline__ uint32_t f2tf(float x) {
    uint32_t r; asm("cvt.rna.tf32.f32 %0, %1;" : "=r"(r) : "f"(x)); return r;
}
__device__ __forceinline__ void mma_tf32(float c[4], uint32_t a0, uint32_t a1,
                                         uint32_t a2, uint32_t a3, uint32_t b0, uint32_t b1) {
    asm volatile("mma.sync.aligned.m16n8k8.row.col.f32.tf32.tf32.f32 "
        "{%0,%1,%2,%3}, {%4,%5,%6,%7}, {%8,%9}, {%0,%1,%2,%3};\n"
        : "+f"(c[0]), "+f"(c[1]), "+f"(c[2]), "+f"(c[3])
        : "r"(a0), "r"(a1), "r"(a2), "r"(a3), "r"(b0), "r"(b1));
}
__device__ __forceinline__ void cp16(void* s, const void* g) {
    uint32_t d = (uint32_t)__cvta_generic_to_shared(s);
    asm volatile("cp.async.ca.shared.global [%0], [%1], 16;\n" :: "r"(d), "l"(g));
}
#define CP_COMMIT() asm volatile("cp.async.commit_group;\n" ::: "memory")
#define CP_WAIT0()  asm volatile("cp.async.wait_group 0;\n" ::: "memory")
#define CP_WAIT1()  asm volatile("cp.async.wait_group 1;\n" ::: "memory")

// ---------------------------------------------------------------------------
// Kernel 0a: X -> A-frag tf32 (g_xt2). frag = {ks=f&1, mt=(f>>1)&1, wm=f>>2}
// uint4 = (A[r0][k0], A[r0+8][k0], A[r0][k0+4], A[r0+8][k0+4])
// ---------------------------------------------------------------------------
__global__ __launch_bounds__(256) void cvt_x2(const float* __restrict__ X)
{
    const int total = 64 * 64 * 512;
    int i = blockIdx.x * blockDim.x + threadIdx.x;
    for (; i < total; i += gridDim.x * blockDim.x) {
        const int lane = i & 31, frag = (i >> 5) & 15, kc = (i >> 9) & 63, mblk = i >> 15;
        const int ks = frag & 1, mt = (frag >> 1) & 1, wm = frag >> 2;
        const int g = lane >> 2, t4 = lane & 3;
        const int r0 = mblk * 128 + wm * 32 + mt * 16 + g;
        const int k0 = kc * 16 + ks * 8 + t4;
        const float* p = X + (size_t)r0 * Dn + k0;
        g_xt2[i] = make_uint4(f2tf(p[0]), f2tf(p[8 * Dn]), f2tf(p[4]), f2tf(p[8 * Dn + 4]));
    }
}

// ---------------------------------------------------------------------------
// Kernel 0b: QKV weights -> B-frag tf32 (g_wt2). frag = {nt=f&7, wn=f>>3}
// words at k offsets t4, t4+4, 8+t4, 12+t4
// ---------------------------------------------------------------------------
__global__ __launch_bounds__(256) void cvt_w2(
    const float* __restrict__ Wq, const float* __restrict__ Wk,
    const float* __restrict__ Wv)
{
    const int total = 24 * 64 * 512;
    int i = blockIdx.x * blockDim.x + threadIdx.x;
    for (; i < total; i += gridDim.x * blockDim.x) {
        const int lane = i & 31, frag = (i >> 5) & 15, kc = (i >> 9) & 63, blk = i >> 15;
        const int which = blk >> 3, nb = blk & 7;
        const int nt = frag & 7, wn = frag >> 3;
        const int g = lane >> 2, t4 = lane & 3;
        const int n_local = wn * 64 + nt * 8 + g;
        const int head = nb * 2 + (n_local >= 64 ? 1 : 0);
        const int e = n_local & 63;
        const float* W = (which == 0) ? Wq : (which == 1) ? Wk : Wv;
        const float* p = W + ((size_t)head * Dn + kc * 16) * HSn + e;
        g_wt2[i] = make_uint4(f2tf(p[(size_t)t4 * HSn]), f2tf(p[(size_t)(t4 + 4) * HSn]),
                              f2tf(p[(size_t)(8 + t4) * HSn]), f2tf(p[(size_t)(12 + t4) * HSn]));
    }
}

// ---------------------------------------------------------------------------
// Kernel 0c: Wo -> B-frag tf32 (g_wo2). Same frag def as cvt_w2 but
// Wo is [k][n] row-major with n stride 1, ld = Dn.
// ---------------------------------------------------------------------------
__global__ __launch_bounds__(256) void cvt_wo2(const float* __restrict__ Wo)
{
    const int total = 8 * 64 * 512;
    int i = blockIdx.x * blockDim.x + threadIdx.x;
    for (; i < total; i += gridDim.x * blockDim.x) {
        const int lane = i & 31, frag = (i >> 5) & 15, kc = (i >> 9) & 63, nblk = i >> 15;
        const int nt = frag & 7, wn = frag >> 3;
        const int g = lane >> 2, t4 = lane & 3;
        const int n = nblk * 128 + wn * 64 + nt * 8 + g;
        const int k0 = kc * 16 + t4;
        const float* p = Wo + (size_t)k0 * Dn + n;
        g_wo2[i] = make_uint4(f2tf(p[0]), f2tf(p[4 * Dn]), f2tf(p[8 * Dn]), f2tf(p[12 * Dn]));
    }
}

// ---------------------------------------------------------------------------
// Kernel P1: K,V -> attn B-frags (g_kf, g_vf). Runs after proj.
// K frag = {nt=f>>2, kp=f&3}: uint4 = K[n][kp*16 + {t4, t4+4, 8+t4, 12+t4}],
//   n = jt*32 + nt*8 + g.
// V frag = {nt=f>>1, kp=f&1}: uint4 = V[jt*32+kp*16 + {t4,t4+4,8+t4,12+t4}][hs],
//   hs = nt*8 + g.
// ---------------------------------------------------------------------------
__global__ __launch_bounds__(256) void perm_kv()
{
    const int total = 64 * 64 * 512;
    int i = blockIdx.x * blockDim.x + threadIdx.x;
    for (; i < 2 * total; i += gridDim.x * blockDim.x) {
        const bool isV = i >= total;
        const int j = isV ? i - total : i;
        const int lane = j & 31, frag = (j >> 5) & 15, jt = (j >> 9) & 63, bh = j >> 15;
        const int g = lane >> 2, t4 = lane & 3;
        if (!isV) {
            const int nt = frag >> 2, kp = frag & 3;
            const int n = jt * 32 + nt * 8 + g;
            const uint32_t* p = g_k + ((size_t)bh * Sn + n) * HSn + kp * 16 + t4;
            g_kf[j] = make_uint4(p[0], p[4], p[8], p[12]);
        } else {
            const int nt = frag >> 1, kp = frag & 1;
            const int hs = nt * 8 + g;
            const int k0 = jt * 32 + kp * 16 + t4;
            const uint32_t* p = g_v + ((size_t)bh * Sn + k0) * HSn + hs;
            g_vf[j] = make_uint4(p[0], p[4 * HSn], p[8 * HSn], p[12 * HSn]);
        }
    }
}

// ---------------------------------------------------------------------------
// Kernel P2: g_attn -> A-frags (g_at2). Runs after attn. Same layout as g_xt2.
// ---------------------------------------------------------------------------
__global__ __launch_bounds__(256) void perm_at()
{
    const int total = 64 * 64 * 512;
    int i = blockIdx.x * blockDim.x + threadIdx.x;
    for (; i < total; i += gridDim.x * blockDim.x) {
        const int lane = i & 31, frag = (i >> 5) & 15, kc = (i >> 9) & 63, mblk = i >> 15;
        const int ks = frag & 1, mt = (frag >> 1) & 1, wm = frag >> 2;
        const int g = lane >> 2, t4 = lane & 3;
        const int r0 = mblk * 128 + wm * 32 + mt * 16 + g;
        const int k0 = kc * 16 + ks * 8 + t4;
        const uint32_t* p = g_attn + (size_t)r0 * Dn + k0;
        g_at2[i] = make_uint4(p[0], p[8 * Dn], p[4], p[8 * Dn + 4]);
    }
}

// ---------------------------------------------------------------------------
// Kernel 1: merged QKV projection (R11-exact winner). grid (24, 64), block 256.
// ---------------------------------------------------------------------------
__global__ __launch_bounds__(256) void proj_tc()
{
    const int xx = blockIdx.x;
    const int which = xx >> 3;
    const int nb = xx & 7;
    const int mblk = blockIdx.y;
    const int m0 = mblk * 128;
    const int b = m0 >> 11;
    const int s0 = m0 & 2047;

    uint32_t* outb = (which == 0) ? g_q : (which == 1) ? g_k : g_v;
    const uint4* Asrc = g_xt2 + (size_t)mblk * 64 * 512;
    const uint4* Bsrc = g_wt2 + (size_t)xx * 64 * 512;

    __shared__ uint4 As4[2][512];
    __shared__ uint4 Bs4[2][512];

    const int tid = threadIdx.x, lane = tid & 31, w = tid >> 5;
    const int wm = w >> 1, wn = w & 1;
    const int g = lane >> 2, t4 = lane & 3;

    float c[2][8][4] = {};

    cp16(&As4[0][tid],       Asrc + tid);
    cp16(&As4[0][tid + 256], Asrc + tid + 256);
    cp16(&Bs4[0][tid],       Bsrc + tid);
    cp16(&Bs4[0][tid + 256], Bsrc + tid + 256);
    CP_COMMIT();
    CP_WAIT0();
    __syncthreads();

    int buf = 0;
    for (int ch = 0; ch < 64; ch++) {
        const bool more = (ch + 1 < 64);
        if (more) {
            const uint4* as = Asrc + (size_t)(ch + 1) * 512;
            const uint4* bs = Bsrc + (size_t)(ch + 1) * 512;
            const int nbuf = buf ^ 1;
            cp16(&As4[nbuf][tid],       as + tid);
            cp16(&As4[nbuf][tid + 256], as + tid + 256);
            cp16(&Bs4[nbuf][tid],       bs + tid);
            cp16(&Bs4[nbuf][tid + 256], bs + tid + 256);
            CP_COMMIT();
        }

        uint4 af[2][2];
        #pragma unroll
        for (int mt = 0; mt < 2; mt++)
            #pragma unroll
            for (int ks = 0; ks < 2; ks++)
                af[mt][ks] = As4[buf][(((wm * 2 + mt) * 2) + ks) * 32 + lane];

        #pragma unroll
        for (int nt = 0; nt < 8; nt++) {
            uint4 bf = Bs4[buf][(wn * 8 + nt) * 32 + lane];
            mma_tf32(c[0][nt], af[0][0].x, af[0][0].y, af[0][0].z, af[0][0].w, bf.x, bf.y);
            mma_tf32(c[1][nt], af[1][0].x, af[1][0].y, af[1][0].z, af[1][0].w, bf.x, bf.y);
            mma_tf32(c[0][nt], af[0][1].x, af[0][1].y, af[0][1].z, af[0][1].w, bf.z, bf.w);
            mma_tf32(c[1][nt], af[1][1].x, af[1][1].y, af[1][1].z, af[1][1].w, bf.z, bf.w);
        }

        if (more) CP_WAIT0();
        __syncthreads();
        buf ^= 1;
    }

    const float sc = (which == 0) ? 0.125f : 1.0f;
    const int h0 = nb * 2;
    uint32_t* O = outb + ((size_t)(b * Hn + h0 + wn) * Sn + s0) * HSn;
    #pragma unroll
    for (int mt = 0; mt < 2; mt++) {
        const int r = wm * 32 + mt * 16 + g;
        #pragma unroll
        for (int nt = 0; nt < 8; nt++) {
            const int hs = nt * 8 + 2 * t4;
            *(uint2*)&O[(size_t)r * HSn + hs] =
                make_uint2(f2tf(c[mt][nt][0] * sc), f2tf(c[mt][nt][1] * sc));
            *(uint2*)&O[(size_t)(r + 8) * HSn + hs] =
                make_uint2(f2tf(c[mt][nt][2] * sc), f2tf(c[mt][nt][3] * sc));
        }
    }
}

// ---------------------------------------------------------------------------
// Kernel 2: causal flash attention with fragment-ordered K/V.
// grid (16, 64), block 256. Accumulation order identical to R6/R11.
// ---------------------------------------------------------------------------
__global__ __launch_bounds__(256) void attn_tc()
{
    const int qt = blockIdx.x, bh = blockIdx.y;
    const int b = bh >> 4, h = bh & 15, q0 = qt * 128;
    const uint32_t* Q = g_q + (size_t)(bh * Sn + q0) * HSn;
    const uint4* Kfg = g_kf + (size_t)bh * 64 * 512;
    const uint4* Vfg = g_vf + (size_t)bh * 64 * 512;

    __shared__ uint4 Kf[2][512];
    __shared__ uint4 Vf[2][512];

    const int tid = threadIdx.x, lane = tid & 31, w = tid >> 5;
    const int g = lane >> 2, t4 = lane & 3, wrow = w * 16;

    uint32_t qf[8][4];
    {
        const uint32_t* Qw = Q + (size_t)(wrow + g) * HSn;
        #pragma unroll
        for (int ks = 0; ks < 8; ks++) {
            const int e = ks * 8 + t4;
            qf[ks][0] = Qw[e];           qf[ks][1] = Qw[8 * HSn + e];
            qf[ks][2] = Qw[e + 4];       qf[ks][3] = Qw[8 * HSn + e + 4];
        }
    }
    float o[8][4] = {};
    float m0 = -1e30f, m1 = -1e30f, l0 = 0.0f, l1 = 0.0f;
    const int rmax = q0 + wrow + 15, jmax = 4 * qt + 3;
    const int srcA = (lane & ~3) | (t4 >> 1), srcB = srcA + 2;
    const bool hi = (t4 & 1) != 0;

    // prime stage 0 with tile 0
    cp16(&Kf[0][tid],       Kfg + tid);
    cp16(&Kf[0][tid + 256], Kfg + tid + 256);
    cp16(&Vf[0][tid],       Vfg + tid);
    cp16(&Vf[0][tid + 256], Vfg + tid + 256);
    CP_COMMIT();

    for (int j = 0; j <= jmax; j++) {
        const int st = j & 1, k0 = j * 32;
        if (j < jmax) {
            const uint4* kp_ = Kfg + (size_t)(j + 1) * 512;
            const uint4* vp_ = Vfg + (size_t)(j + 1) * 512;
            const int ns = st ^ 1;
            cp16(&Kf[ns][tid],       kp_ + tid);
            cp16(&Kf[ns][tid + 256], kp_ + tid + 256);
            cp16(&Vf[ns][tid],       vp_ + tid);
            cp16(&Vf[ns][tid + 256], vp_ + tid + 256);
            CP_COMMIT(); CP_WAIT1();
        } else { CP_WAIT0(); }
        __syncthreads();

        if (k0 <= rmax) {
            // S = Q @ K^T : 16 LDS.128
            float s[4][4] = {};
            #pragma unroll
            for (int nt = 0; nt < 4; nt++) {
                #pragma unroll
                for (int kp = 0; kp < 4; kp++) {
                    uint4 kf = Kf[st][(nt * 4 + kp) * 32 + lane];
                    const int ks0 = 2 * kp;
                    mma_tf32(s[nt], qf[ks0][0], qf[ks0][1], qf[ks0][2], qf[ks0][3], kf.x, kf.y);
                    mma_tf32(s[nt], qf[ks0 + 1][0], qf[ks0 + 1][1], qf[ks0 + 1][2], qf[ks0 + 1][3], kf.z, kf.w);
                }
            }

            const int r0g = q0 + wrow + g, r1g = r0g + 8;
            #pragma unroll
            for (int nt = 0; nt < 4; nt++) {
                const int kc0 = k0 + nt * 8 + 2 * t4;
                if (kc0 > r0g)     s[nt][0] = -1e30f;
                if (kc0 + 1 > r0g) s[nt][1] = -1e30f;
                if (kc0 > r1g)     s[nt][2] = -1e30f;
                if (kc0 + 1 > r1g) s[nt][3] = -1e30f;
            }
            float mx0 = -1e30f, mx1 = -1e30f;
            #pragma unroll
            for (int nt = 0; nt < 4; nt++) {
                mx0 = fmaxf(mx0, fmaxf(s[nt][0], s[nt][1]));
                mx1 = fmaxf(mx1, fmaxf(s[nt][2], s[nt][3]));
            }
            mx0 = fmaxf(mx0, __shfl_xor_sync(~0u, mx0, 1));
            mx0 = fmaxf(mx0, __shfl_xor_sync(~0u, mx0, 2));
            mx1 = fmaxf(mx1, __shfl_xor_sync(~0u, mx1, 1));
            mx1 = fmaxf(mx1, __shfl_xor_sync(~0u, mx1, 2));
            const float mn0 = fmaxf(m0, mx0), mn1 = fmaxf(m1, mx1);
            const float al0 = __expf(m0 - mn0), al1 = __expf(m1 - mn1);
            m0 = mn0; m1 = mn1;

            uint32_t pt[4][4];
            float sum0 = 0.0f, sum1 = 0.0f;
            #pragma unroll
            for (int nt = 0; nt < 4; nt++) {
                float p0 = __expf(s[nt][0] - m0), p1 = __expf(s[nt][1] - m0);
                float p2 = __expf(s[nt][2] - m1), p3 = __expf(s[nt][3] - m1);
                pt[nt][0] = f2tf(p0); pt[nt][1] = f2tf(p1);
                pt[nt][2] = f2tf(p2); pt[nt][3] = f2tf(p3);
                sum0 += __uint_as_float(pt[nt][0]) + __uint_as_float(pt[nt][1]);
                sum1 += __uint_as_float(pt[nt][2]) + __uint_as_float(pt[nt][3]);
            }
            sum0 += __shfl_xor_sync(~0u, sum0, 1); sum0 += __shfl_xor_sync(~0u, sum0, 2);
            sum1 += __shfl_xor_sync(~0u, sum1, 1); sum1 += __shfl_xor_sync(~0u, sum1, 2);
            l0 = l0 * al0 + sum0; l1 = l1 * al1 + sum1;

            #pragma unroll
            for (int nt = 0; nt < 8; nt++) {
                o[nt][0] *= al0; o[nt][1] *= al0;
                o[nt][2] *= al1; o[nt][3] *= al1;
            }

            // C->A relayout for all 4 ksteps first
            uint32_t aa[4][4];
            #pragma unroll
            for (int ks = 0; ks < 4; ks++) {
                uint32_t p0a = __shfl_sync(~0u, pt[ks][0], srcA);
                uint32_t p1a = __shfl_sync(~0u, pt[ks][1], srcA);
                uint32_t p2a = __shfl_sync(~0u, pt[ks][2], srcA);
                uint32_t p3a = __shfl_sync(~0u, pt[ks][3], srcA);
                uint32_t p0b = __shfl_sync(~0u, pt[ks][0], srcB);
                uint32_t p1b = __shfl_sync(~0u, pt[ks][1], srcB);
                uint32_t p2b = __shfl_sync(~0u, pt[ks][2], srcB);
                uint32_t p3b = __shfl_sync(~0u, pt[ks][3], srcB);
                aa[ks][0] = hi ? p1a : p0a;
                aa[ks][1] = hi ? p3a : p2a;
                aa[ks][2] = hi ? p1b : p0b;
                aa[ks][3] = hi ? p3b : p2b;
            }

            // O += P @ V : 16 LDS.128; ks order per o[nt] = 0,1,2,3 (unchanged)
            #pragma unroll
            for (int nt = 0; nt < 8; nt++) {
                #pragma unroll
                for (int kp = 0; kp < 2; kp++) {
                    uint4 vf = Vf[st][(nt * 2 + kp) * 32 + lane];
                    const int ks0 = 2 * kp;
                    mma_tf32(o[nt], aa[ks0][0], aa[ks0][1], aa[ks0][2], aa[ks0][3], vf.x, vf.y);
                    mma_tf32(o[nt], aa[ks0 + 1][0], aa[ks0 + 1][1], aa[ks0 + 1][2], aa[ks0 + 1][3], vf.z, vf.w);
                }
            }
        }
        __syncthreads();
    }
    const float inv0 = 1.0f / l0, inv1 = 1.0f / l1;
    const int row = q0 + wrow + g;
    uint32_t* Ob = g_attn + (size_t)(b * Sn) * Dn + h * HSn;
    #pragma unroll
    for (int nt = 0; nt < 8; nt++) {
        const int hs = nt * 8 + 2 * t4;
        *(uint2*)&Ob[(size_t)row * Dn + hs] =
            make_uint2(f2tf(o[nt][0] * inv0), f2tf(o[nt][1] * inv0));
        *(uint2*)&Ob[(size_t)(row + 8) * Dn + hs] =
            make_uint2(f2tf(o[nt][2] * inv1), f2tf(o[nt][3] * inv1));
    }
}

// ---------------------------------------------------------------------------
// Kernel 3: output projection, fragment-ordered (proj template).
// grid (8, 64), block 256.
// ---------------------------------------------------------------------------
__global__ __launch_bounds__(256) void outproj_tc(
    const float* __restrict__ bo, float* __restrict__ out)
{
    const int nblk = blockIdx.x;
    const int mblk = blockIdx.y;
    const int m0 = mblk * 128;
    const uint4* Asrc = g_at2 + (size_t)mblk * 64 * 512;
    const uint4* Bsrc = g_wo2 + (size_t)nblk * 64 * 512;

    __shared__ uint4 As4[2][512];
    __shared__ uint4 Bs4[2][512];

    const int tid = threadIdx.x, lane = tid & 31, w = tid >> 5;
    const int wm = w >> 1, wn = w & 1;
    const int g = lane >> 2, t4 = lane & 3;

    float c[2][8][4] = {};

    cp16(&As4[0][tid],       Asrc + tid);
    cp16(&As4[0][tid + 256], Asrc + tid + 256);
    cp16(&Bs4[0][tid],       Bsrc + tid);
    cp16(&Bs4[0][tid + 256], Bsrc + tid + 256);
    CP_COMMIT();
    CP_WAIT0();
    __syncthreads();

    int buf = 0;
    for (int ch = 0; ch < 64; ch++) {
        const bool more = (ch + 1 < 64);
        if (more) {
            const uint4* as = Asrc + (size_t)(ch + 1) * 512;
            const uint4* bs = Bsrc + (size_t)(ch + 1) * 512;
            const int nbuf = buf ^ 1;
            cp16(&As4[nbuf][tid],       as + tid);
            cp16(&As4[nbuf][tid + 256], as + tid + 256);
            cp16(&Bs4[nbuf][tid],       bs + tid);
            cp16(&Bs4[nbuf][tid + 256], bs + tid + 256);
            CP_COMMIT();
        }

        uint4 af[2][2];
        #pragma unroll
        for (int mt = 0; mt < 2; mt++)
            #pragma unroll
            for (int ks = 0; ks < 2; ks++)
                af[mt][ks] = As4[buf][(((wm * 2 + mt) * 2) + ks) * 32 + lane];

        #pragma unroll
        for (int nt = 0; nt < 8; nt++) {
            uint4 bf = Bs4[buf][(wn * 8 + nt) * 32 + lane];
            mma_tf32(c[0][nt], af[0][0].x, af[0][0].y, af[0][0].z, af[0][0].w, bf.x, bf.y);
            mma_tf32(c[1][nt], af[1][0].x, af[1][0].y, af[1][0].z, af[1][0].w, bf.x, bf.y);
            mma_tf32(c[0][nt], af[0][1].x, af[0][1].y, af[0][1].z, af[0][1].w, bf.z, bf.w);
            mma_tf32(c[1][nt], af[1][1].x, af[1][1].y, af[1][1].z, af[1][1].w, bf.z, bf.w);
        }

        if (more) CP_WAIT0();
        __syncthreads();
        buf ^= 1;
    }

    float* C = out + (size_t)m0 * Dn + nblk * 128;
    #pragma unroll
    for (int mt = 0; mt < 2; mt++) {
        const int r = wm * 32 + mt * 16 + g;
        #pragma unroll
        for (int nt = 0; nt < 8; nt++) {
            const int n = wn * 64 + nt * 8 + 2 * t4;
            const float2 bias = *(const float2*)&bo[nblk * 128 + n];
            *(float2*)&C[(size_t)r * Dn + n] =
                make_float2(c[mt][nt][0] + bias.x, c[mt][nt][1] + bias.y);
            *(float2*)&C[(size_t)(r + 8) * Dn + n] =
                make_float2(c[mt][nt][2] + bias.x, c[mt][nt][3] + bias.y);
        }
    }
}

// ---------------------------------------------------------------------------
extern "C" void kernel_launch(void* const* d_in, const int* in_sizes, int n_in,
                              void* d_out, int out_size)
{
    const float* X  = (const float*)d_in[0];
    const float* Wq = (const float*)d_in[1];
    const float* Wk = (const float*)d_in[2];
    const float* Wv = (const float*)d_in[3];
    const float* Wo = (const float*)d_in[4];
    const float* bo = (const float*)d_in[5];
    float* out = (float*)d_out;

    cvt_x2<<<2048, 256>>>(X);
    cvt_w2<<<1024, 256>>>(Wq, Wk, Wv);
    cvt_wo2<<<256, 256>>>(Wo);
    proj_tc<<<dim3(24, 64), 256>>>();
    perm_kv<<<2048, 256>>>();
    attn_tc<<<dim3(16, 64), 256>>>();
    perm_at<<<2048, 256>>>();
    outproj_tc<<<dim3(8, 64), 256>>>(bo, out);
}